// round 10
// baseline (speedup 1.0000x reference)
#include <cuda_runtime.h>
#include <cuda_bf16.h>
#include <math.h>
#include <cstdint>

// ---------------------------------------------------------------------------
// FieldPredictionNetwork:  B=32768, G=512, H0=1024, H1=512, W=64, MODES=32, FD=128
// MLP GEMMs: mma.sync bf16 hi/lo split, CTA 128x128, 3-stage cp.async,
//            phased A-frag lifetimes (no spills).
// FFT: precomputed twiddles; mid/out: coalesced padded weight smem.
// ---------------------------------------------------------------------------

#define NB 32768

// -------------------- scratch (device globals) ------------------------------
__device__ __nv_bfloat16 g_geomhi[NB * 512],  g_geomlo[NB * 512];
__device__ __nv_bfloat16 g_Winhi[1024 * 512], g_Winlo[1024 * 512];
__device__ __nv_bfloat16 g_Wh1hi[512 * 1024], g_Wh1lo[512 * 1024];
__device__ __nv_bfloat16 g_Wh2hi[64 * 512],   g_Wh2lo[64 * 512];
__device__ __nv_bfloat16 g_h0hi[NB * 1024],   g_h0lo[NB * 1024];
__device__ __nv_bfloat16 g_h1hi[NB * 512],    g_h1lo[NB * 512];
__device__ float  g_xr[NB * 64];
__device__ float2 g_bufA[NB * 64];
__device__ float2 g_bufB[NB * 64];
__device__ float2 g_Z[NB * 64];
__device__ float2 g_dftF[64 * 64];
__device__ float2 g_dftI[64 * 64];
__device__ float2 g_P[64];
__device__ float2 g_M[64];
__device__ float2 g_stw1[256];
__device__ float2 g_stw2[128];
__device__ float2 g_btw[32768];

// -------------------- small PTX wrappers ------------------------------------
__device__ __forceinline__ uint32_t smem_u32(const void* p) {
    uint32_t a;
    asm("{ .reg .u64 t; cvta.to.shared.u64 t, %1; cvt.u32.u64 %0, t; }" : "=r"(a) : "l"(p));
    return a;
}
__device__ __forceinline__ void ldsm_x4(uint32_t* r, uint32_t a) {
    asm volatile("ldmatrix.sync.aligned.m8n8.x4.shared.b16 {%0,%1,%2,%3}, [%4];"
                 : "=r"(r[0]), "=r"(r[1]), "=r"(r[2]), "=r"(r[3]) : "r"(a));
}
__device__ __forceinline__ void mma16816(float* c, const uint32_t* a,
                                         uint32_t b0, uint32_t b1) {
    asm volatile("mma.sync.aligned.m16n8k16.row.col.f32.bf16.bf16.f32 "
                 "{%0,%1,%2,%3}, {%4,%5,%6,%7}, {%8,%9}, {%0,%1,%2,%3};"
                 : "+f"(c[0]), "+f"(c[1]), "+f"(c[2]), "+f"(c[3])
                 : "r"(a[0]), "r"(a[1]), "r"(a[2]), "r"(a[3]), "r"(b0), "r"(b1));
}
__device__ __forceinline__ void cp16(uint32_t dst, const void* src) {
    asm volatile("cp.async.cg.shared.global [%0], [%1], 16;" :: "r"(dst), "l"(src));
}
#define CP_COMMIT()  asm volatile("cp.async.commit_group;" ::: "memory")
#define CP_WAIT(n)   asm volatile("cp.async.wait_group %0;" :: "n"(n) : "memory")

// 16B-chunk XOR swizzle: row r (bf16 row of 32 elems = 4 chunks), chunk cc.
#define SWOFF(r, cc) ((uint32_t)((r) * 64 + (((cc) ^ (((r) >> 1) & 3)) << 4)))

// -------------------- fp32 -> bf16 hi/lo split ------------------------------
template <int SEL>
__global__ void split_kernel(const float* __restrict__ src, int n4)
{
    __nv_bfloat16* hi = (SEL == 0) ? g_geomhi : (SEL == 1) ? g_Winhi : (SEL == 2) ? g_Wh1hi : g_Wh2hi;
    __nv_bfloat16* lo = (SEL == 0) ? g_geomlo : (SEL == 1) ? g_Winlo : (SEL == 2) ? g_Wh1lo : g_Wh2lo;
    int i = blockIdx.x * blockDim.x + threadIdx.x;
    if (i >= n4) return;
    float4 v = reinterpret_cast<const float4*>(src)[i];
    __nv_bfloat16 h0 = __float2bfloat16(v.x), h1 = __float2bfloat16(v.y);
    __nv_bfloat16 h2 = __float2bfloat16(v.z), h3 = __float2bfloat16(v.w);
    __nv_bfloat162 a, b;
    a.x = h0; a.y = h1; b.x = h2; b.y = h3;
    reinterpret_cast<__nv_bfloat162*>(hi)[2 * i]     = a;
    reinterpret_cast<__nv_bfloat162*>(hi)[2 * i + 1] = b;
    a.x = __float2bfloat16(v.x - __bfloat162float(h0));
    a.y = __float2bfloat16(v.y - __bfloat162float(h1));
    b.x = __float2bfloat16(v.z - __bfloat162float(h2));
    b.y = __float2bfloat16(v.w - __bfloat162float(h3));
    reinterpret_cast<__nv_bfloat162*>(lo)[2 * i]     = a;
    reinterpret_cast<__nv_bfloat162*>(lo)[2 * i + 1] = b;
}

// -------------------- mma.sync bf16-split GEMM + bias + relu ----------------
// C[M,N] = relu(A[M,K] @ B[N,K]^T + bias).  CTA 128 x BN, BK=32, 3-stage
// cp.async.  8 warps = 2(m) x 4(n); warp tile 64 x (BN/4).
// A-fragments are phased (hi then lo reuse the same registers) to keep the
// kernel under the 128-reg cap without spills.
template <int BN, int SEL>
__global__ void __launch_bounds__(256, 2)
mma_gemm(const float* __restrict__ bias, int M, int N, int K)
{
    const __nv_bfloat16* Ahi = (SEL == 0) ? g_geomhi : (SEL == 1) ? g_h0hi : g_h1hi;
    const __nv_bfloat16* Alo = (SEL == 0) ? g_geomlo : (SEL == 1) ? g_h0lo : g_h1lo;
    const __nv_bfloat16* Bhi = (SEL == 0) ? g_Winhi  : (SEL == 1) ? g_Wh1hi : g_Wh2hi;
    const __nv_bfloat16* Blo = (SEL == 0) ? g_Winlo  : (SEL == 1) ? g_Wh1lo : g_Wh2lo;

    constexpr int ASTG = 8192;          // 128 rows x 32 bf16
    constexpr int BSTG = BN * 64;       // BN rows x 32 bf16
    constexpr int WN   = BN / 4;        // warp n width (16 or 32)
    constexpr int NFR  = WN / 16;       // B ldsm_x4 per hi/lo: 1 (BN=64) or 2 (BN=128)
    constexpr int NNI  = WN / 8;        // n8 frags per warp: 2 (BN=64) or 4 (BN=128)

    extern __shared__ __align__(16) char dsm[];
    const uint32_t sb  = smem_u32(dsm);
    const uint32_t bAh = sb;
    const uint32_t bAl = sb + 3 * ASTG;
    const uint32_t bBh = sb + 6 * ASTG;
    const uint32_t bBl = bBh + 3 * BSTG;

    const int tid = threadIdx.x;
    const int warp = tid >> 5, lane = tid & 31;
    const int wm = warp >> 2, wn = warp & 3;
    const int m0 = blockIdx.y * 128, n0 = blockIdx.x * BN;

    float acc[4][NNI][4];
#pragma unroll
    for (int i = 0; i < 4; i++)
#pragma unroll
        for (int j = 0; j < NNI; j++)
#pragma unroll
            for (int q = 0; q < 4; q++) acc[i][j][q] = 0.f;

    const int row_off = (lane & 7) | (((lane >> 3) & 1) << 3);
    const int cc_half = lane >> 4;
    const int ldr = tid >> 2, ldc = tid & 3;
    const uint32_t oA0 = SWOFF(ldr, ldc), oA1 = SWOFF(ldr + 64, ldc);
    const int nchunk = K >> 5;

#define LOAD_STAGE(kc, bf) do {                                                 \
        int _k0 = (kc) << 5;                                                    \
        uint32_t _oa = (uint32_t)(bf) * ASTG, _ob = (uint32_t)(bf) * BSTG;      \
        size_t _g0 = (size_t)(m0 + ldr) * K + _k0 + ldc * 8;                    \
        size_t _g1 = (size_t)(m0 + ldr + 64) * K + _k0 + ldc * 8;               \
        cp16(bAh + _oa + oA0, Ahi + _g0);                                       \
        cp16(bAh + _oa + oA1, Ahi + _g1);                                       \
        cp16(bAl + _oa + oA0, Alo + _g0);                                       \
        cp16(bAl + _oa + oA1, Alo + _g1);                                       \
        size_t _gb0 = (size_t)(n0 + ldr) * K + _k0 + ldc * 8;                   \
        cp16(bBh + _ob + oA0, Bhi + _gb0);                                      \
        cp16(bBl + _ob + oA0, Blo + _gb0);                                      \
        if (BN == 128) {                                                        \
            size_t _gb1 = (size_t)(n0 + ldr + 64) * K + _k0 + ldc * 8;          \
            cp16(bBh + _ob + oA1, Bhi + _gb1);                                  \
            cp16(bBl + _ob + oA1, Blo + _gb1);                                  \
        }                                                                       \
    } while (0)

    LOAD_STAGE(0, 0); CP_COMMIT();
    LOAD_STAGE(1, 1); CP_COMMIT();

    for (int kc = 0; kc < nchunk; kc++) {
        const int bf = kc % 3;
        if (kc + 2 < nchunk) {
            LOAD_STAGE(kc + 2, (kc + 2) % 3);
            CP_COMMIT();
            CP_WAIT(2);
        } else if (kc + 1 < nchunk) {
            CP_WAIT(1);
        } else {
            CP_WAIT(0);
        }
        __syncthreads();
        const uint32_t oa = (uint32_t)bf * ASTG, ob = (uint32_t)bf * BSTG;
#pragma unroll
        for (int s = 0; s < 2; s++) {
            const int cc = 2 * s + cc_half;
            uint32_t Bfh[4 * NFR], Bfl[4 * NFR];
#pragma unroll
            for (int f = 0; f < NFR; f++) {
                int r = wn * WN + f * 16 + row_off;
                ldsm_x4(Bfh + 4 * f, bBh + ob + SWOFF(r, cc));
                ldsm_x4(Bfl + 4 * f, bBl + ob + SWOFF(r, cc));
            }
            uint32_t Af[4][4];
            // ---- hi phase: A_hi x (B_hi, B_lo) ----
#pragma unroll
            for (int mi = 0; mi < 4; mi++) {
                int r = wm * 64 + mi * 16 + row_off;
                ldsm_x4(Af[mi], bAh + oa + SWOFF(r, cc));
            }
#pragma unroll
            for (int mi = 0; mi < 4; mi++) {
#pragma unroll
                for (int ni = 0; ni < NNI; ni++) {
                    const int q = (ni >> 1) * 4 + (ni & 1);
                    mma16816(acc[mi][ni], Af[mi], Bfh[q], Bfh[q + 2]);
                    mma16816(acc[mi][ni], Af[mi], Bfl[q], Bfl[q + 2]);
                }
            }
            // ---- lo phase: A_lo x B_hi (Af registers reused) ----
#pragma unroll
            for (int mi = 0; mi < 4; mi++) {
                int r = wm * 64 + mi * 16 + row_off;
                ldsm_x4(Af[mi], bAl + oa + SWOFF(r, cc));
            }
#pragma unroll
            for (int mi = 0; mi < 4; mi++) {
#pragma unroll
                for (int ni = 0; ni < NNI; ni++) {
                    const int q = (ni >> 1) * 4 + (ni & 1);
                    mma16816(acc[mi][ni], Af[mi], Bfh[q], Bfh[q + 2]);
                }
            }
        }
        __syncthreads();
    }
#undef LOAD_STAGE

    // ---- epilogue: bias + relu (+ hi/lo re-split for SEL 0/1) ----
    const int g = lane >> 2, tg = lane & 3;
#pragma unroll
    for (int mi = 0; mi < 4; mi++) {
#pragma unroll
        for (int ni = 0; ni < NNI; ni++) {
            int col = n0 + wn * WN + ni * 8 + 2 * tg;
            float b0 = bias[col], b1 = bias[col + 1];
#pragma unroll
            for (int h = 0; h < 2; h++) {
                int row = m0 + wm * 64 + mi * 16 + g + h * 8;
                float v0 = acc[mi][ni][2 * h + 0] + b0;
                float v1 = acc[mi][ni][2 * h + 1] + b1;
                v0 = v0 > 0.f ? v0 : 0.f;
                v1 = v1 > 0.f ? v1 : 0.f;
                size_t idx = (size_t)row * N + col;
                if (SEL == 2) {
                    *reinterpret_cast<float2*>(g_xr + idx) = make_float2(v0, v1);
                } else {
                    __nv_bfloat16* Chi = (SEL == 0) ? g_h0hi : g_h1hi;
                    __nv_bfloat16* Clo = (SEL == 0) ? g_h0lo : g_h1lo;
                    __nv_bfloat162 hh, ll;
                    hh.x = __float2bfloat16(v0);
                    hh.y = __float2bfloat16(v1);
                    ll.x = __float2bfloat16(v0 - __bfloat162float(hh.x));
                    ll.y = __float2bfloat16(v1 - __bfloat162float(hh.y));
                    *reinterpret_cast<__nv_bfloat162*>(Chi + idx) = hh;
                    *reinterpret_cast<__nv_bfloat162*>(Clo + idx) = ll;
                }
            }
        }
    }
}

// -------------------- table init (grid-stride, double precision) ------------
__global__ void init_tables(const float* __restrict__ w0,
                            const float* __restrict__ w1)
{
    const double TWO_PI = 6.283185307179586476925286766559;
    const double PI = 3.1415926535897932384626433832795;
    int gtid = blockIdx.x * blockDim.x + threadIdx.x;
    int nthr = gridDim.x * blockDim.x;
    for (int i = gtid; i < 32768; i += nthr) {
        double s, c;
        sincos(-TWO_PI * (double)i / 32768.0, &s, &c);
        g_btw[i] = make_float2((float)c, (float)s);
    }
    for (int i = gtid; i < 255; i += nthr) {
        int v = i + 1;
        int p = 31 - __clz(v);
        int Ns = 1 << p, jm = v - Ns;
        double s, c;
        sincos(-PI * (double)jm / (double)Ns, &s, &c);
        g_stw1[i] = make_float2((float)c, (float)s);
    }
    for (int i = gtid; i < 127; i += nthr) {
        int v = i + 1;
        int p = 31 - __clz(v);
        int Ns = 1 << p, jm = v - Ns;
        double s, c;
        sincos(-PI * (double)jm / (double)Ns, &s, &c);
        g_stw2[i] = make_float2((float)c, (float)s);
    }
    for (int i = gtid; i < 4096; i += nthr) {
        int a = i >> 6, b = i & 63;
        int t = (a * b) & 63;
        double s, c;
        sincos(-TWO_PI * (double)t / 64.0, &s, &c);
        g_dftF[i] = make_float2((float)c, (float)s);
        g_dftI[i] = make_float2((float)(c / 64.0), (float)(-s / 64.0));
    }
    for (int w = gtid; w < 64; w += nthr) {
        double pr = 0, pi = 0, mr = 0, mi = 0;
        for (int m = 0; m < 32; m++) {
            float a = w0[m * 64 + w];
            float b = w1[m * 64 + w];
            double s, c;
            sincos(TWO_PI * (double)m / 32.0, &s, &c);
            double coef = (double)b * fabs((double)a);
            if (a >= 0.0f) { pr += coef * c; pi += coef * s; }
            else           { mr += coef * c; mi += coef * s; }
        }
        g_P[w] = make_float2((float)pr, (float)pi);
        g_M[w] = make_float2((float)mr, (float)mi);
    }
}

// -------------------- per-row forward DFT-64 --------------------------------
__global__ __launch_bounds__(1024)
void fwd_row_dft()
{
    __shared__ float sx[16][64];
    int tid = threadIdx.x;
    int row0 = blockIdx.x << 4;
    for (int i = tid; i < 16 * 64; i += 1024)
        sx[i >> 6][i & 63] = g_xr[(size_t)(row0 + (i >> 6)) * 64 + (i & 63)];
    __syncthreads();
    int r = tid >> 6, k = tid & 63;
    float re = 0.f, im = 0.f;
#pragma unroll 16
    for (int w = 0; w < 64; w++) {
        float2 t = g_dftF[(w << 6) + k];
        float xv = sx[r][w];
        re = fmaf(xv, t.x, re);
        im = fmaf(xv, t.y, im);
    }
    g_bufA[(size_t)(row0 + r) * 64 + k] = make_float2(re, im);
}

// -------------------- batch-axis FFT, step 1 (fs=+1 fwd, -1 inv) ------------
__global__ __launch_bounds__(256)
void fft_b_step1(float fs)
{
    __shared__ float2 s0[8][256];
    __shared__ float2 s1[8][256];
    __shared__ float2 stw[255];
    int tid = threadIdx.x;
    int n1 = blockIdx.x;
    int c0 = blockIdx.y << 3;
    for (int i = tid; i < 255; i += 256) stw[i] = g_stw1[i];
    for (int i = tid; i < 2048; i += 256) {
        int n2 = i >> 3, ch = i & 7;
        s0[ch][n2] = g_bufA[(size_t)(n1 + (n2 << 7)) * 64 + c0 + ch];
    }
    __syncthreads();
    float2 (*src)[256] = s0;
    float2 (*dst)[256] = s1;
#pragma unroll
    for (int p = 0; p < 8; p++) {
        int Ns = 1 << p;
        for (int u = tid; u < 1024; u += 256) {
            int ch = u >> 7, j = u & 127;
            int jm = j & (Ns - 1);
            float2 a = src[ch][j];
            float2 b = src[ch][j + 128];
            float2 tw = stw[Ns - 1 + jm];
            float c = tw.x, s = fs * tw.y;
            float2 bw = make_float2(b.x * c - b.y * s, b.x * s + b.y * c);
            int idxD = ((j - jm) << 1) + jm;
            dst[ch][idxD]      = make_float2(a.x + bw.x, a.y + bw.y);
            dst[ch][idxD + Ns] = make_float2(a.x - bw.x, a.y - bw.y);
        }
        __syncthreads();
        float2 (*tmp)[256] = src; src = dst; dst = tmp;
    }
    for (int i = tid; i < 2048; i += 256) {
        int k2 = i >> 3, ch = i & 7;
        float2 w = g_btw[(n1 * k2) & 32767];
        float c = w.x, s = fs * w.y;
        float2 v = src[ch][k2];
        g_Z[((size_t)k2 * 128 + n1) * 64 + c0 + ch] =
            make_float2(v.x * c - v.y * s, v.x * s + v.y * c);
    }
}

// -------------------- batch-axis FFT, step 2 --------------------------------
__global__ __launch_bounds__(256)
void fft_b_step2(float fs, float scale)
{
    __shared__ float2 s0[8][128];
    __shared__ float2 s1[8][128];
    __shared__ float2 stw[127];
    int tid = threadIdx.x;
    int k2 = blockIdx.x;
    int c0 = blockIdx.y << 3;
    for (int i = tid; i < 127; i += 256) stw[i] = g_stw2[i];
    for (int i = tid; i < 1024; i += 256) {
        int n1 = i >> 3, ch = i & 7;
        s0[ch][n1] = g_Z[((size_t)k2 * 128 + n1) * 64 + c0 + ch];
    }
    __syncthreads();
    float2 (*src)[128] = s0;
    float2 (*dst)[128] = s1;
#pragma unroll
    for (int p = 0; p < 7; p++) {
        int Ns = 1 << p;
        for (int u = tid; u < 512; u += 256) {
            int ch = u >> 6, j = u & 63;
            int jm = j & (Ns - 1);
            float2 a = src[ch][j];
            float2 b = src[ch][j + 64];
            float2 tw = stw[Ns - 1 + jm];
            float c = tw.x, s = fs * tw.y;
            float2 bw = make_float2(b.x * c - b.y * s, b.x * s + b.y * c);
            int idxD = ((j - jm) << 1) + jm;
            dst[ch][idxD]      = make_float2(a.x + bw.x, a.y + bw.y);
            dst[ch][idxD + Ns] = make_float2(a.x - bw.x, a.y - bw.y);
        }
        __syncthreads();
        float2 (*tmp)[128] = src; src = dst; dst = tmp;
    }
    for (int i = tid; i < 1024; i += 256) {
        int k1 = i >> 3, ch = i & 7;
        float2 v = src[ch][k1];
        g_bufB[(size_t)(k2 + (k1 << 8)) * 64 + c0 + ch] =
            make_float2(v.x * scale, v.y * scale);
    }
}

// -------------------- FNO core (16 rows/block, padded weights) --------------
__global__ __launch_bounds__(1024)
void mid_kernel(const float* __restrict__ lin1W, const float* __restrict__ lin1b,
                const float* __restrict__ lin2W, const float* __restrict__ lin2b)
{
    __shared__ float L1t[64 * 65];
    __shared__ float L2t[64 * 65];
    __shared__ float yre[16][64], yim[16][64];
    __shared__ float2 sP[64], sM[64];
    int tid = threadIdx.x;
    int row0 = blockIdx.x << 4;
    for (int i = tid; i < 4096; i += 1024) {
        int o = i >> 6, w = i & 63;
        L1t[o * 65 + w] = lin1W[i];
        L2t[o * 65 + w] = lin2W[i];
    }
    if (tid < 64) { sP[tid] = g_P[tid]; sM[tid] = g_M[tid]; }
    int r = tid >> 6, w = tid & 63;
    float2 xh = g_bufB[(size_t)(row0 + r) * 64 + w];
    __syncthreads();
    {
        float rp = fmaxf(xh.x, 0.f), rn = fmaxf(-xh.x, 0.f);
        float ip = fmaxf(xh.y, 0.f), im2 = fmaxf(-xh.y, 0.f);
        float2 P = sP[w], Mv = sM[w];
        yre[r][w] = rp * P.x - ip * P.y + rn * Mv.x - im2 * Mv.y;
        yim[r][w] = rp * P.y + ip * P.x + rn * Mv.y + im2 * Mv.x;
    }
    __syncthreads();
    int o = w;
    float re = lin1b[o], im = 0.f;
#pragma unroll 16
    for (int ww = 0; ww < 64; ww++) {
        float lw = L1t[o * 65 + ww];
        re = fmaf(lw, yre[r][ww], re);
        im = fmaf(lw, yim[r][ww], im);
    }
    re = fmaxf(re, 0.f);
    im = fmaxf(im, 0.f);
    __syncthreads();
    yre[r][o] = re;
    yim[r][o] = im;
    __syncthreads();
    re = lin2b[o]; im = 0.f;
#pragma unroll 16
    for (int ww = 0; ww < 64; ww++) {
        float lw = L2t[o * 65 + ww];
        re = fmaf(lw, yre[r][ww], re);
        im = fmaf(lw, yim[r][ww], im);
    }
    g_bufA[(size_t)(row0 + r) * 64 + o] = make_float2(re, im);
}

// -------------------- inverse row DFT-64 + W_out (16 rows/block) ------------
__global__ __launch_bounds__(1024)
void out_kernel(const float* __restrict__ Wout, const float* __restrict__ bout,
                float* __restrict__ outp, int interleaved)
{
    __shared__ float Wt[128 * 65];
    __shared__ float2 szu[16][64];
    int tid = threadIdx.x;
    int row0 = blockIdx.x << 4;
    for (int i = tid; i < 8192; i += 1024) {
        int f = i >> 6, w = i & 63;
        Wt[f * 65 + w] = Wout[i];
    }
    {
        int r = tid >> 6, k = tid & 63;
        szu[r][k] = g_bufB[(size_t)(row0 + r) * 64 + k];
    }
    __syncthreads();
    float ure, uim;
    {
        int r = tid >> 6, w = tid & 63;
        float re = 0.f, im = 0.f;
#pragma unroll 16
        for (int k = 0; k < 64; k++) {
            float2 t = g_dftI[(k << 6) + w];
            float2 z = szu[r][k];
            re += z.x * t.x - z.y * t.y;
            im += z.x * t.y + z.y * t.x;
        }
        ure = re; uim = im;
    }
    __syncthreads();
    {
        int r = tid >> 6, w = tid & 63;
        szu[r][w] = make_float2(ure, uim);
    }
    __syncthreads();
#pragma unroll
    for (int it = 0; it < 2; it++) {
        int idx = it * 1024 + tid;
        int r = idx >> 7, f = idx & 127;
        float re = bout[f], im = 0.f;
#pragma unroll 16
        for (int w = 0; w < 64; w++) {
            float lw = Wt[f * 65 + w];
            float2 u = szu[r][w];
            re = fmaf(lw, u.x, re);
            im = fmaf(lw, u.y, im);
        }
        size_t oidx = (size_t)(row0 + r) * 128 + f;
        if (interleaved) {
            reinterpret_cast<float2*>(outp)[oidx] = make_float2(re, im);
        } else {
            outp[oidx] = re;
        }
    }
}

// ---------------------------------------------------------------------------
extern "C" void kernel_launch(void* const* d_in, const int* in_sizes, int n_in,
                              void* d_out, int out_size)
{
    (void)in_sizes; (void)n_in;
    const float* geom  = (const float*)d_in[0];
    const float* W_in  = (const float*)d_in[1];
    const float* b_in  = (const float*)d_in[2];
    const float* W_h1  = (const float*)d_in[3];
    const float* b_h1  = (const float*)d_in[4];
    const float* W_h2  = (const float*)d_in[5];
    const float* b_h2  = (const float*)d_in[6];
    const float* w0    = (const float*)d_in[7];
    const float* w1    = (const float*)d_in[8];
    const float* lin1W = (const float*)d_in[9];
    const float* lin1b = (const float*)d_in[10];
    const float* lin2W = (const float*)d_in[11];
    const float* lin2b = (const float*)d_in[12];
    const float* Wout  = (const float*)d_in[13];
    const float* bout  = (const float*)d_in[14];

    const int GSM128 = 6 * 8192 + 6 * 128 * 64;   // 98304 bytes (BN=128)
    const int GSM64  = 6 * 8192 + 6 * 64 * 64;    // 73728 bytes (BN=64)
    cudaFuncSetAttribute(mma_gemm<128, 0>, cudaFuncAttributeMaxDynamicSharedMemorySize, GSM128);
    cudaFuncSetAttribute(mma_gemm<128, 1>, cudaFuncAttributeMaxDynamicSharedMemorySize, GSM128);
    cudaFuncSetAttribute(mma_gemm<64, 2>,  cudaFuncAttributeMaxDynamicSharedMemorySize, GSM64);

    init_tables<<<64, 256>>>(w0, w1);

    // splits + GEMMs (mma_gemm<128,0> stays in the ncu capture slot)
    split_kernel<0><<<(NB * 512 / 4) / 256, 256>>>(geom, NB * 512 / 4);
    split_kernel<1><<<(1024 * 512 / 4) / 256, 256>>>(W_in, 1024 * 512 / 4);
    mma_gemm<128, 0><<<dim3(1024 / 128, NB / 128), 256, GSM128>>>(b_in, NB, 1024, 512);
    split_kernel<2><<<(512 * 1024 / 4) / 256, 256>>>(W_h1, 512 * 1024 / 4);
    mma_gemm<128, 1><<<dim3(512 / 128, NB / 128), 256, GSM128>>>(b_h1, NB, 512, 1024);
    split_kernel<3><<<(64 * 512 / 4) / 256, 256>>>(W_h2, 64 * 512 / 4);
    mma_gemm<64, 2><<<dim3(1, NB / 128), 256, GSM64>>>(b_h2, NB, 64, 512);

    // forward fftn
    fwd_row_dft<<<NB / 16, 1024>>>();
    fft_b_step1<<<dim3(128, 8), 256>>>(1.f);
    fft_b_step2<<<dim3(256, 8), 256>>>(1.f, 1.0f);

    // FNO core
    mid_kernel<<<NB / 16, 1024>>>(lin1W, lin1b, lin2W, lin2b);

    // inverse batch-axis FFT (conjugated twiddles)
    fft_b_step1<<<dim3(128, 8), 256>>>(-1.f);
    fft_b_step2<<<dim3(256, 8), 256>>>(-1.f, 1.0f / 32768.0f);

    // inverse row DFT-64 + output projection
    int interleaved = (out_size >= 2 * NB * 128) ? 1 : 0;
    out_kernel<<<NB / 16, 1024>>>(Wout, bout, (float*)d_out, interleaved);
}

// round 11
// speedup vs baseline: 1.5464x; 1.5464x over previous
#include <cuda_runtime.h>
#include <cuda_bf16.h>
#include <math.h>
#include <cstdint>

// ---------------------------------------------------------------------------
// FieldPredictionNetwork:  B=32768, G=512, H0=1024, H1=512, W=64, MODES=32, FD=128
// MLP GEMMs: mma.sync bf16 hi/lo split, CTA 128x128, 3-stage cp.async,
//            ONE barrier per K-chunk.
// FFT: precomputed twiddles; mid/out: coalesced padded weight smem.
// ---------------------------------------------------------------------------

#define NB 32768

// -------------------- scratch (device globals) ------------------------------
__device__ __nv_bfloat16 g_geomhi[NB * 512],  g_geomlo[NB * 512];
__device__ __nv_bfloat16 g_Winhi[1024 * 512], g_Winlo[1024 * 512];
__device__ __nv_bfloat16 g_Wh1hi[512 * 1024], g_Wh1lo[512 * 1024];
__device__ __nv_bfloat16 g_Wh2hi[64 * 512],   g_Wh2lo[64 * 512];
__device__ __nv_bfloat16 g_h0hi[NB * 1024],   g_h0lo[NB * 1024];
__device__ __nv_bfloat16 g_h1hi[NB * 512],    g_h1lo[NB * 512];
__device__ float  g_xr[NB * 64];
__device__ float2 g_bufA[NB * 64];
__device__ float2 g_bufB[NB * 64];
__device__ float2 g_Z[NB * 64];
__device__ float2 g_dftF[64 * 64];
__device__ float2 g_dftI[64 * 64];
__device__ float2 g_P[64];
__device__ float2 g_M[64];
__device__ float2 g_stw1[256];
__device__ float2 g_stw2[128];
__device__ float2 g_btw[32768];

// -------------------- small PTX wrappers ------------------------------------
__device__ __forceinline__ uint32_t smem_u32(const void* p) {
    uint32_t a;
    asm("{ .reg .u64 t; cvta.to.shared.u64 t, %1; cvt.u32.u64 %0, t; }" : "=r"(a) : "l"(p));
    return a;
}
__device__ __forceinline__ void ldsm_x4(uint32_t* r, uint32_t a) {
    asm volatile("ldmatrix.sync.aligned.m8n8.x4.shared.b16 {%0,%1,%2,%3}, [%4];"
                 : "=r"(r[0]), "=r"(r[1]), "=r"(r[2]), "=r"(r[3]) : "r"(a));
}
__device__ __forceinline__ void mma16816(float* c, const uint32_t* a,
                                         uint32_t b0, uint32_t b1) {
    asm volatile("mma.sync.aligned.m16n8k16.row.col.f32.bf16.bf16.f32 "
                 "{%0,%1,%2,%3}, {%4,%5,%6,%7}, {%8,%9}, {%0,%1,%2,%3};"
                 : "+f"(c[0]), "+f"(c[1]), "+f"(c[2]), "+f"(c[3])
                 : "r"(a[0]), "r"(a[1]), "r"(a[2]), "r"(a[3]), "r"(b0), "r"(b1));
}
__device__ __forceinline__ void cp16(uint32_t dst, const void* src) {
    asm volatile("cp.async.cg.shared.global [%0], [%1], 16;" :: "r"(dst), "l"(src));
}
#define CP_COMMIT()  asm volatile("cp.async.commit_group;" ::: "memory")
#define CP_WAIT(n)   asm volatile("cp.async.wait_group %0;" :: "n"(n) : "memory")

// 16B-chunk XOR swizzle: row r (bf16 row of 32 elems = 4 chunks), chunk cc.
#define SWOFF(r, cc) ((uint32_t)((r) * 64 + (((cc) ^ (((r) >> 1) & 3)) << 4)))

// -------------------- fp32 -> bf16 hi/lo split ------------------------------
template <int SEL>
__global__ void split_kernel(const float* __restrict__ src, int n4)
{
    __nv_bfloat16* hi = (SEL == 0) ? g_geomhi : (SEL == 1) ? g_Winhi : (SEL == 2) ? g_Wh1hi : g_Wh2hi;
    __nv_bfloat16* lo = (SEL == 0) ? g_geomlo : (SEL == 1) ? g_Winlo : (SEL == 2) ? g_Wh1lo : g_Wh2lo;
    int i = blockIdx.x * blockDim.x + threadIdx.x;
    if (i >= n4) return;
    float4 v = reinterpret_cast<const float4*>(src)[i];
    __nv_bfloat16 h0 = __float2bfloat16(v.x), h1 = __float2bfloat16(v.y);
    __nv_bfloat16 h2 = __float2bfloat16(v.z), h3 = __float2bfloat16(v.w);
    __nv_bfloat162 a, b;
    a.x = h0; a.y = h1; b.x = h2; b.y = h3;
    reinterpret_cast<__nv_bfloat162*>(hi)[2 * i]     = a;
    reinterpret_cast<__nv_bfloat162*>(hi)[2 * i + 1] = b;
    a.x = __float2bfloat16(v.x - __bfloat162float(h0));
    a.y = __float2bfloat16(v.y - __bfloat162float(h1));
    b.x = __float2bfloat16(v.z - __bfloat162float(h2));
    b.y = __float2bfloat16(v.w - __bfloat162float(h3));
    reinterpret_cast<__nv_bfloat162*>(lo)[2 * i]     = a;
    reinterpret_cast<__nv_bfloat162*>(lo)[2 * i + 1] = b;
}

// -------------------- mma.sync bf16-split GEMM + bias + relu ----------------
// C[M,N] = relu(A[M,K] @ B[N,K]^T + bias).  CTA 128 x BN, BK=32, 3-stage
// cp.async, ONE __syncthreads per chunk:
//   top-of-iter barrier (after CP_WAIT) both publishes stage kc to all
//   threads AND certifies everyone finished computing kc-1, making it safe
//   to overwrite buffer (kc+2)%3 == (kc-1)%3 right after it.
template <int BN, int SEL>
__global__ void __launch_bounds__(256, 2)
mma_gemm(const float* __restrict__ bias, int M, int N, int K)
{
    const __nv_bfloat16* Ahi = (SEL == 0) ? g_geomhi : (SEL == 1) ? g_h0hi : g_h1hi;
    const __nv_bfloat16* Alo = (SEL == 0) ? g_geomlo : (SEL == 1) ? g_h0lo : g_h1lo;
    const __nv_bfloat16* Bhi = (SEL == 0) ? g_Winhi  : (SEL == 1) ? g_Wh1hi : g_Wh2hi;
    const __nv_bfloat16* Blo = (SEL == 0) ? g_Winlo  : (SEL == 1) ? g_Wh1lo : g_Wh2lo;

    constexpr int ASTG = 8192;          // 128 rows x 32 bf16
    constexpr int BSTG = BN * 64;       // BN rows x 32 bf16
    constexpr int WN   = BN / 4;        // warp n width (16 or 32)
    constexpr int NFR  = WN / 16;       // B ldsm_x4 per hi/lo: 1 (BN=64) or 2 (BN=128)
    constexpr int NNI  = WN / 8;        // n8 frags per warp: 2 (BN=64) or 4 (BN=128)

    extern __shared__ __align__(16) char dsm[];
    const uint32_t sb  = smem_u32(dsm);
    const uint32_t bAh = sb;
    const uint32_t bAl = sb + 3 * ASTG;
    const uint32_t bBh = sb + 6 * ASTG;
    const uint32_t bBl = bBh + 3 * BSTG;

    const int tid = threadIdx.x;
    const int warp = tid >> 5, lane = tid & 31;
    const int wm = warp >> 2, wn = warp & 3;
    const int m0 = blockIdx.y * 128, n0 = blockIdx.x * BN;

    float acc[4][NNI][4];
#pragma unroll
    for (int i = 0; i < 4; i++)
#pragma unroll
        for (int j = 0; j < NNI; j++)
#pragma unroll
            for (int q = 0; q < 4; q++) acc[i][j][q] = 0.f;

    const int row_off = (lane & 7) | (((lane >> 3) & 1) << 3);
    const int cc_half = lane >> 4;
    const int ldr = tid >> 2, ldc = tid & 3;
    const uint32_t oA0 = SWOFF(ldr, ldc), oA1 = SWOFF(ldr + 64, ldc);
    const int nchunk = K >> 5;

#define LOAD_STAGE(kc, bf) do {                                                 \
        int _k0 = (kc) << 5;                                                    \
        uint32_t _oa = (uint32_t)(bf) * ASTG, _ob = (uint32_t)(bf) * BSTG;      \
        size_t _g0 = (size_t)(m0 + ldr) * K + _k0 + ldc * 8;                    \
        size_t _g1 = (size_t)(m0 + ldr + 64) * K + _k0 + ldc * 8;               \
        cp16(bAh + _oa + oA0, Ahi + _g0);                                       \
        cp16(bAh + _oa + oA1, Ahi + _g1);                                       \
        cp16(bAl + _oa + oA0, Alo + _g0);                                       \
        cp16(bAl + _oa + oA1, Alo + _g1);                                       \
        size_t _gb0 = (size_t)(n0 + ldr) * K + _k0 + ldc * 8;                   \
        cp16(bBh + _ob + oA0, Bhi + _gb0);                                      \
        cp16(bBl + _ob + oA0, Blo + _gb0);                                      \
        if (BN == 128) {                                                        \
            size_t _gb1 = (size_t)(n0 + ldr + 64) * K + _k0 + ldc * 8;          \
            cp16(bBh + _ob + oA1, Bhi + _gb1);                                  \
            cp16(bBl + _ob + oA1, Blo + _gb1);                                  \
        }                                                                       \
    } while (0)

    LOAD_STAGE(0, 0); CP_COMMIT();
    LOAD_STAGE(1, 1); CP_COMMIT();

    for (int kc = 0; kc < nchunk; kc++) {
        // stage kc completion: the only younger committed group is kc+1.
        if (kc + 1 < nchunk) { CP_WAIT(1); } else { CP_WAIT(0); }
        __syncthreads();   // publish stage kc; certifies compute(kc-1) done
        if (kc + 2 < nchunk) {
            LOAD_STAGE(kc + 2, (kc + 2) % 3);   // overwrites (kc-1)%3: safe
            CP_COMMIT();
        }
        const int bf = kc % 3;
        const uint32_t oa = (uint32_t)bf * ASTG, ob = (uint32_t)bf * BSTG;
#pragma unroll
        for (int s = 0; s < 2; s++) {
            const int cc = 2 * s + cc_half;
            uint32_t Afh[4][4], Afl[4][4], Bfh[4 * NFR], Bfl[4 * NFR];
#pragma unroll
            for (int mi = 0; mi < 4; mi++) {
                int r = wm * 64 + mi * 16 + row_off;
                ldsm_x4(Afh[mi], bAh + oa + SWOFF(r, cc));
                ldsm_x4(Afl[mi], bAl + oa + SWOFF(r, cc));
            }
#pragma unroll
            for (int f = 0; f < NFR; f++) {
                int r = wn * WN + f * 16 + row_off;
                ldsm_x4(Bfh + 4 * f, bBh + ob + SWOFF(r, cc));
                ldsm_x4(Bfl + 4 * f, bBl + ob + SWOFF(r, cc));
            }
#pragma unroll
            for (int mi = 0; mi < 4; mi++) {
#pragma unroll
                for (int ni = 0; ni < NNI; ni++) {
                    const int q = (ni >> 1) * 4 + (ni & 1);
                    mma16816(acc[mi][ni], Afh[mi], Bfh[q], Bfh[q + 2]);
                    mma16816(acc[mi][ni], Afh[mi], Bfl[q], Bfl[q + 2]);
                    mma16816(acc[mi][ni], Afl[mi], Bfh[q], Bfh[q + 2]);
                }
            }
        }
    }
#undef LOAD_STAGE

    // ---- epilogue: bias + relu (+ hi/lo re-split for SEL 0/1) ----
    const int g = lane >> 2, tg = lane & 3;
#pragma unroll
    for (int mi = 0; mi < 4; mi++) {
#pragma unroll
        for (int ni = 0; ni < NNI; ni++) {
            int col = n0 + wn * WN + ni * 8 + 2 * tg;
            float b0 = bias[col], b1 = bias[col + 1];
#pragma unroll
            for (int h = 0; h < 2; h++) {
                int row = m0 + wm * 64 + mi * 16 + g + h * 8;
                float v0 = acc[mi][ni][2 * h + 0] + b0;
                float v1 = acc[mi][ni][2 * h + 1] + b1;
                v0 = v0 > 0.f ? v0 : 0.f;
                v1 = v1 > 0.f ? v1 : 0.f;
                size_t idx = (size_t)row * N + col;
                if (SEL == 2) {
                    *reinterpret_cast<float2*>(g_xr + idx) = make_float2(v0, v1);
                } else {
                    __nv_bfloat16* Chi = (SEL == 0) ? g_h0hi : g_h1hi;
                    __nv_bfloat16* Clo = (SEL == 0) ? g_h0lo : g_h1lo;
                    __nv_bfloat162 hh, ll;
                    hh.x = __float2bfloat16(v0);
                    hh.y = __float2bfloat16(v1);
                    ll.x = __float2bfloat16(v0 - __bfloat162float(hh.x));
                    ll.y = __float2bfloat16(v1 - __bfloat162float(hh.y));
                    *reinterpret_cast<__nv_bfloat162*>(Chi + idx) = hh;
                    *reinterpret_cast<__nv_bfloat162*>(Clo + idx) = ll;
                }
            }
        }
    }
}

// -------------------- table init (grid-stride, double precision) ------------
__global__ void init_tables(const float* __restrict__ w0,
                            const float* __restrict__ w1)
{
    const double TWO_PI = 6.283185307179586476925286766559;
    const double PI = 3.1415926535897932384626433832795;
    int gtid = blockIdx.x * blockDim.x + threadIdx.x;
    int nthr = gridDim.x * blockDim.x;
    for (int i = gtid; i < 32768; i += nthr) {
        double s, c;
        sincos(-TWO_PI * (double)i / 32768.0, &s, &c);
        g_btw[i] = make_float2((float)c, (float)s);
    }
    for (int i = gtid; i < 255; i += nthr) {
        int v = i + 1;
        int p = 31 - __clz(v);
        int Ns = 1 << p, jm = v - Ns;
        double s, c;
        sincos(-PI * (double)jm / (double)Ns, &s, &c);
        g_stw1[i] = make_float2((float)c, (float)s);
    }
    for (int i = gtid; i < 127; i += nthr) {
        int v = i + 1;
        int p = 31 - __clz(v);
        int Ns = 1 << p, jm = v - Ns;
        double s, c;
        sincos(-PI * (double)jm / (double)Ns, &s, &c);
        g_stw2[i] = make_float2((float)c, (float)s);
    }
    for (int i = gtid; i < 4096; i += nthr) {
        int a = i >> 6, b = i & 63;
        int t = (a * b) & 63;
        double s, c;
        sincos(-TWO_PI * (double)t / 64.0, &s, &c);
        g_dftF[i] = make_float2((float)c, (float)s);
        g_dftI[i] = make_float2((float)(c / 64.0), (float)(-s / 64.0));
    }
    for (int w = gtid; w < 64; w += nthr) {
        double pr = 0, pi = 0, mr = 0, mi = 0;
        for (int m = 0; m < 32; m++) {
            float a = w0[m * 64 + w];
            float b = w1[m * 64 + w];
            double s, c;
            sincos(TWO_PI * (double)m / 32.0, &s, &c);
            double coef = (double)b * fabs((double)a);
            if (a >= 0.0f) { pr += coef * c; pi += coef * s; }
            else           { mr += coef * c; mi += coef * s; }
        }
        g_P[w] = make_float2((float)pr, (float)pi);
        g_M[w] = make_float2((float)mr, (float)mi);
    }
}

// -------------------- per-row forward DFT-64 --------------------------------
__global__ __launch_bounds__(1024)
void fwd_row_dft()
{
    __shared__ float sx[16][64];
    int tid = threadIdx.x;
    int row0 = blockIdx.x << 4;
    for (int i = tid; i < 16 * 64; i += 1024)
        sx[i >> 6][i & 63] = g_xr[(size_t)(row0 + (i >> 6)) * 64 + (i & 63)];
    __syncthreads();
    int r = tid >> 6, k = tid & 63;
    float re = 0.f, im = 0.f;
#pragma unroll 16
    for (int w = 0; w < 64; w++) {
        float2 t = g_dftF[(w << 6) + k];
        float xv = sx[r][w];
        re = fmaf(xv, t.x, re);
        im = fmaf(xv, t.y, im);
    }
    g_bufA[(size_t)(row0 + r) * 64 + k] = make_float2(re, im);
}

// -------------------- batch-axis FFT, step 1 (fs=+1 fwd, -1 inv) ------------
__global__ __launch_bounds__(256)
void fft_b_step1(float fs)
{
    __shared__ float2 s0[8][256];
    __shared__ float2 s1[8][256];
    __shared__ float2 stw[255];
    int tid = threadIdx.x;
    int n1 = blockIdx.x;
    int c0 = blockIdx.y << 3;
    for (int i = tid; i < 255; i += 256) stw[i] = g_stw1[i];
    for (int i = tid; i < 2048; i += 256) {
        int n2 = i >> 3, ch = i & 7;
        s0[ch][n2] = g_bufA[(size_t)(n1 + (n2 << 7)) * 64 + c0 + ch];
    }
    __syncthreads();
    float2 (*src)[256] = s0;
    float2 (*dst)[256] = s1;
#pragma unroll
    for (int p = 0; p < 8; p++) {
        int Ns = 1 << p;
        for (int u = tid; u < 1024; u += 256) {
            int ch = u >> 7, j = u & 127;
            int jm = j & (Ns - 1);
            float2 a = src[ch][j];
            float2 b = src[ch][j + 128];
            float2 tw = stw[Ns - 1 + jm];
            float c = tw.x, s = fs * tw.y;
            float2 bw = make_float2(b.x * c - b.y * s, b.x * s + b.y * c);
            int idxD = ((j - jm) << 1) + jm;
            dst[ch][idxD]      = make_float2(a.x + bw.x, a.y + bw.y);
            dst[ch][idxD + Ns] = make_float2(a.x - bw.x, a.y - bw.y);
        }
        __syncthreads();
        float2 (*tmp)[256] = src; src = dst; dst = tmp;
    }
    for (int i = tid; i < 2048; i += 256) {
        int k2 = i >> 3, ch = i & 7;
        float2 w = g_btw[(n1 * k2) & 32767];
        float c = w.x, s = fs * w.y;
        float2 v = src[ch][k2];
        g_Z[((size_t)k2 * 128 + n1) * 64 + c0 + ch] =
            make_float2(v.x * c - v.y * s, v.x * s + v.y * c);
    }
}

// -------------------- batch-axis FFT, step 2 --------------------------------
__global__ __launch_bounds__(256)
void fft_b_step2(float fs, float scale)
{
    __shared__ float2 s0[8][128];
    __shared__ float2 s1[8][128];
    __shared__ float2 stw[127];
    int tid = threadIdx.x;
    int k2 = blockIdx.x;
    int c0 = blockIdx.y << 3;
    for (int i = tid; i < 127; i += 256) stw[i] = g_stw2[i];
    for (int i = tid; i < 1024; i += 256) {
        int n1 = i >> 3, ch = i & 7;
        s0[ch][n1] = g_Z[((size_t)k2 * 128 + n1) * 64 + c0 + ch];
    }
    __syncthreads();
    float2 (*src)[128] = s0;
    float2 (*dst)[128] = s1;
#pragma unroll
    for (int p = 0; p < 7; p++) {
        int Ns = 1 << p;
        for (int u = tid; u < 512; u += 256) {
            int ch = u >> 6, j = u & 63;
            int jm = j & (Ns - 1);
            float2 a = src[ch][j];
            float2 b = src[ch][j + 64];
            float2 tw = stw[Ns - 1 + jm];
            float c = tw.x, s = fs * tw.y;
            float2 bw = make_float2(b.x * c - b.y * s, b.x * s + b.y * c);
            int idxD = ((j - jm) << 1) + jm;
            dst[ch][idxD]      = make_float2(a.x + bw.x, a.y + bw.y);
            dst[ch][idxD + Ns] = make_float2(a.x - bw.x, a.y - bw.y);
        }
        __syncthreads();
        float2 (*tmp)[128] = src; src = dst; dst = tmp;
    }
    for (int i = tid; i < 1024; i += 256) {
        int k1 = i >> 3, ch = i & 7;
        float2 v = src[ch][k1];
        g_bufB[(size_t)(k2 + (k1 << 8)) * 64 + c0 + ch] =
            make_float2(v.x * scale, v.y * scale);
    }
}

// -------------------- FNO core (16 rows/block, padded weights) --------------
__global__ __launch_bounds__(1024)
void mid_kernel(const float* __restrict__ lin1W, const float* __restrict__ lin1b,
                const float* __restrict__ lin2W, const float* __restrict__ lin2b)
{
    __shared__ float L1t[64 * 65];
    __shared__ float L2t[64 * 65];
    __shared__ float yre[16][64], yim[16][64];
    __shared__ float2 sP[64], sM[64];
    int tid = threadIdx.x;
    int row0 = blockIdx.x << 4;
    for (int i = tid; i < 4096; i += 1024) {
        int o = i >> 6, w = i & 63;
        L1t[o * 65 + w] = lin1W[i];
        L2t[o * 65 + w] = lin2W[i];
    }
    if (tid < 64) { sP[tid] = g_P[tid]; sM[tid] = g_M[tid]; }
    int r = tid >> 6, w = tid & 63;
    float2 xh = g_bufB[(size_t)(row0 + r) * 64 + w];
    __syncthreads();
    {
        float rp = fmaxf(xh.x, 0.f), rn = fmaxf(-xh.x, 0.f);
        float ip = fmaxf(xh.y, 0.f), im2 = fmaxf(-xh.y, 0.f);
        float2 P = sP[w], Mv = sM[w];
        yre[r][w] = rp * P.x - ip * P.y + rn * Mv.x - im2 * Mv.y;
        yim[r][w] = rp * P.y + ip * P.x + rn * Mv.y + im2 * Mv.x;
    }
    __syncthreads();
    int o = w;
    float re = lin1b[o], im = 0.f;
#pragma unroll 16
    for (int ww = 0; ww < 64; ww++) {
        float lw = L1t[o * 65 + ww];
        re = fmaf(lw, yre[r][ww], re);
        im = fmaf(lw, yim[r][ww], im);
    }
    re = fmaxf(re, 0.f);
    im = fmaxf(im, 0.f);
    __syncthreads();
    yre[r][o] = re;
    yim[r][o] = im;
    __syncthreads();
    re = lin2b[o]; im = 0.f;
#pragma unroll 16
    for (int ww = 0; ww < 64; ww++) {
        float lw = L2t[o * 65 + ww];
        re = fmaf(lw, yre[r][ww], re);
        im = fmaf(lw, yim[r][ww], im);
    }
    g_bufA[(size_t)(row0 + r) * 64 + o] = make_float2(re, im);
}

// -------------------- inverse row DFT-64 + W_out (16 rows/block) ------------
__global__ __launch_bounds__(1024)
void out_kernel(const float* __restrict__ Wout, const float* __restrict__ bout,
                float* __restrict__ outp, int interleaved)
{
    __shared__ float Wt[128 * 65];
    __shared__ float2 szu[16][64];
    int tid = threadIdx.x;
    int row0 = blockIdx.x << 4;
    for (int i = tid; i < 8192; i += 1024) {
        int f = i >> 6, w = i & 63;
        Wt[f * 65 + w] = Wout[i];
    }
    {
        int r = tid >> 6, k = tid & 63;
        szu[r][k] = g_bufB[(size_t)(row0 + r) * 64 + k];
    }
    __syncthreads();
    float ure, uim;
    {
        int r = tid >> 6, w = tid & 63;
        float re = 0.f, im = 0.f;
#pragma unroll 16
        for (int k = 0; k < 64; k++) {
            float2 t = g_dftI[(k << 6) + w];
            float2 z = szu[r][k];
            re += z.x * t.x - z.y * t.y;
            im += z.x * t.y + z.y * t.x;
        }
        ure = re; uim = im;
    }
    __syncthreads();
    {
        int r = tid >> 6, w = tid & 63;
        szu[r][w] = make_float2(ure, uim);
    }
    __syncthreads();
#pragma unroll
    for (int it = 0; it < 2; it++) {
        int idx = it * 1024 + tid;
        int r = idx >> 7, f = idx & 127;
        float re = bout[f], im = 0.f;
#pragma unroll 16
        for (int w = 0; w < 64; w++) {
            float lw = Wt[f * 65 + w];
            float2 u = szu[r][w];
            re = fmaf(lw, u.x, re);
            im = fmaf(lw, u.y, im);
        }
        size_t oidx = (size_t)(row0 + r) * 128 + f;
        if (interleaved) {
            reinterpret_cast<float2*>(outp)[oidx] = make_float2(re, im);
        } else {
            outp[oidx] = re;
        }
    }
}

// ---------------------------------------------------------------------------
extern "C" void kernel_launch(void* const* d_in, const int* in_sizes, int n_in,
                              void* d_out, int out_size)
{
    (void)in_sizes; (void)n_in;
    const float* geom  = (const float*)d_in[0];
    const float* W_in  = (const float*)d_in[1];
    const float* b_in  = (const float*)d_in[2];
    const float* W_h1  = (const float*)d_in[3];
    const float* b_h1  = (const float*)d_in[4];
    const float* W_h2  = (const float*)d_in[5];
    const float* b_h2  = (const float*)d_in[6];
    const float* w0    = (const float*)d_in[7];
    const float* w1    = (const float*)d_in[8];
    const float* lin1W = (const float*)d_in[9];
    const float* lin1b = (const float*)d_in[10];
    const float* lin2W = (const float*)d_in[11];
    const float* lin2b = (const float*)d_in[12];
    const float* Wout  = (const float*)d_in[13];
    const float* bout  = (const float*)d_in[14];

    const int GSM128 = 6 * 8192 + 6 * 128 * 64;   // 98304 bytes (BN=128)
    const int GSM64  = 6 * 8192 + 6 * 64 * 64;    // 73728 bytes (BN=64)
    cudaFuncSetAttribute(mma_gemm<128, 0>, cudaFuncAttributeMaxDynamicSharedMemorySize, GSM128);
    cudaFuncSetAttribute(mma_gemm<128, 1>, cudaFuncAttributeMaxDynamicSharedMemorySize, GSM128);
    cudaFuncSetAttribute(mma_gemm<64, 2>,  cudaFuncAttributeMaxDynamicSharedMemorySize, GSM64);

    init_tables<<<64, 256>>>(w0, w1);

    // splits + GEMMs (mma_gemm<128,0> stays in the ncu capture slot)
    split_kernel<0><<<(NB * 512 / 4) / 256, 256>>>(geom, NB * 512 / 4);
    split_kernel<1><<<(1024 * 512 / 4) / 256, 256>>>(W_in, 1024 * 512 / 4);
    mma_gemm<128, 0><<<dim3(1024 / 128, NB / 128), 256, GSM128>>>(b_in, NB, 1024, 512);
    split_kernel<2><<<(512 * 1024 / 4) / 256, 256>>>(W_h1, 512 * 1024 / 4);
    mma_gemm<128, 1><<<dim3(512 / 128, NB / 128), 256, GSM128>>>(b_h1, NB, 512, 1024);
    split_kernel<3><<<(64 * 512 / 4) / 256, 256>>>(W_h2, 64 * 512 / 4);
    mma_gemm<64, 2><<<dim3(1, NB / 128), 256, GSM64>>>(b_h2, NB, 64, 512);

    // forward fftn
    fwd_row_dft<<<NB / 16, 1024>>>();
    fft_b_step1<<<dim3(128, 8), 256>>>(1.f);
    fft_b_step2<<<dim3(256, 8), 256>>>(1.f, 1.0f);

    // FNO core
    mid_kernel<<<NB / 16, 1024>>>(lin1W, lin1b, lin2W, lin2b);

    // inverse batch-axis FFT (conjugated twiddles)
    fft_b_step1<<<dim3(128, 8), 256>>>(-1.f);
    fft_b_step2<<<dim3(256, 8), 256>>>(-1.f, 1.0f / 32768.0f);

    // inverse row DFT-64 + output projection
    int interleaved = (out_size >= 2 * NB * 128) ? 1 : 0;
    out_kernel<<<NB / 16, 1024>>>(Wout, bout, (float*)d_out, interleaved);
}

// round 12
// speedup vs baseline: 1.5527x; 1.0041x over previous
#include <cuda_runtime.h>
#include <cuda_bf16.h>
#include <math.h>
#include <cstdint>

// ---------------------------------------------------------------------------
// FieldPredictionNetwork:  B=32768, G=512, H0=1024, H1=512, W=64, MODES=32, FD=128
// MLP GEMMs: mma.sync bf16 hi/lo split, CTA 128x128, 3-stage cp.async.
// FFT: batch-axis radix-4 Stockham (256=4^4, 128=2*4^3), precomputed twiddles.
// Row DFT-64 fused into mid/out kernels (DFT axes commute).
// ---------------------------------------------------------------------------

#define NB 32768

// -------------------- scratch (device globals) ------------------------------
__device__ __nv_bfloat16 g_geomhi[NB * 512],  g_geomlo[NB * 512];
__device__ __nv_bfloat16 g_Winhi[1024 * 512], g_Winlo[1024 * 512];
__device__ __nv_bfloat16 g_Wh1hi[512 * 1024], g_Wh1lo[512 * 1024];
__device__ __nv_bfloat16 g_Wh2hi[64 * 512],   g_Wh2lo[64 * 512];
__device__ __nv_bfloat16 g_h0hi[NB * 1024],   g_h0lo[NB * 1024];
__device__ __nv_bfloat16 g_h1hi[NB * 512],    g_h1lo[NB * 512];
__device__ float  g_xr[NB * 64];
__device__ float2 g_bufA[NB * 64];
__device__ float2 g_bufB[NB * 64];
__device__ float2 g_Z[NB * 64];
__device__ float2 g_dftF[64 * 64];
__device__ float2 g_dftI[64 * 64];
__device__ float2 g_P[64];
__device__ float2 g_M[64];
__device__ float2 g_r4a[85 * 3];    // radix-4 twiddles, N=256 (Ns=1,4,16,64)
__device__ float2 g_r4b[42 * 3];    // radix-4 twiddles, N=128 (Ns=2,8,32)
__device__ float2 g_btw[32768];     // e^{-2 pi i t / 32768}

// -------------------- small PTX wrappers ------------------------------------
__device__ __forceinline__ uint32_t smem_u32(const void* p) {
    uint32_t a;
    asm("{ .reg .u64 t; cvta.to.shared.u64 t, %1; cvt.u32.u64 %0, t; }" : "=r"(a) : "l"(p));
    return a;
}
__device__ __forceinline__ void ldsm_x4(uint32_t* r, uint32_t a) {
    asm volatile("ldmatrix.sync.aligned.m8n8.x4.shared.b16 {%0,%1,%2,%3}, [%4];"
                 : "=r"(r[0]), "=r"(r[1]), "=r"(r[2]), "=r"(r[3]) : "r"(a));
}
__device__ __forceinline__ void mma16816(float* c, const uint32_t* a,
                                         uint32_t b0, uint32_t b1) {
    asm volatile("mma.sync.aligned.m16n8k16.row.col.f32.bf16.bf16.f32 "
                 "{%0,%1,%2,%3}, {%4,%5,%6,%7}, {%8,%9}, {%0,%1,%2,%3};"
                 : "+f"(c[0]), "+f"(c[1]), "+f"(c[2]), "+f"(c[3])
                 : "r"(a[0]), "r"(a[1]), "r"(a[2]), "r"(a[3]), "r"(b0), "r"(b1));
}
__device__ __forceinline__ void cp16(uint32_t dst, const void* src) {
    asm volatile("cp.async.cg.shared.global [%0], [%1], 16;" :: "r"(dst), "l"(src));
}
#define CP_COMMIT()  asm volatile("cp.async.commit_group;" ::: "memory")
#define CP_WAIT(n)   asm volatile("cp.async.wait_group %0;" :: "n"(n) : "memory")

// 16B-chunk XOR swizzle: row r (bf16 row of 32 elems = 4 chunks), chunk cc.
#define SWOFF(r, cc) ((uint32_t)((r) * 64 + (((cc) ^ (((r) >> 1) & 3)) << 4)))

// -------------------- fp32 -> bf16 hi/lo split ------------------------------
template <int SEL>
__global__ void split_kernel(const float* __restrict__ src, int n4)
{
    __nv_bfloat16* hi = (SEL == 0) ? g_geomhi : (SEL == 1) ? g_Winhi : (SEL == 2) ? g_Wh1hi : g_Wh2hi;
    __nv_bfloat16* lo = (SEL == 0) ? g_geomlo : (SEL == 1) ? g_Winlo : (SEL == 2) ? g_Wh1lo : g_Wh2lo;
    int i = blockIdx.x * blockDim.x + threadIdx.x;
    if (i >= n4) return;
    float4 v = reinterpret_cast<const float4*>(src)[i];
    __nv_bfloat16 h0 = __float2bfloat16(v.x), h1 = __float2bfloat16(v.y);
    __nv_bfloat16 h2 = __float2bfloat16(v.z), h3 = __float2bfloat16(v.w);
    __nv_bfloat162 a, b;
    a.x = h0; a.y = h1; b.x = h2; b.y = h3;
    reinterpret_cast<__nv_bfloat162*>(hi)[2 * i]     = a;
    reinterpret_cast<__nv_bfloat162*>(hi)[2 * i + 1] = b;
    a.x = __float2bfloat16(v.x - __bfloat162float(h0));
    a.y = __float2bfloat16(v.y - __bfloat162float(h1));
    b.x = __float2bfloat16(v.z - __bfloat162float(h2));
    b.y = __float2bfloat16(v.w - __bfloat162float(h3));
    reinterpret_cast<__nv_bfloat162*>(lo)[2 * i]     = a;
    reinterpret_cast<__nv_bfloat162*>(lo)[2 * i + 1] = b;
}

// -------------------- mma.sync bf16-split GEMM + bias + relu ----------------
template <int BN, int SEL>
__global__ void __launch_bounds__(256, 2)
mma_gemm(const float* __restrict__ bias, int M, int N, int K)
{
    const __nv_bfloat16* Ahi = (SEL == 0) ? g_geomhi : (SEL == 1) ? g_h0hi : g_h1hi;
    const __nv_bfloat16* Alo = (SEL == 0) ? g_geomlo : (SEL == 1) ? g_h0lo : g_h1lo;
    const __nv_bfloat16* Bhi = (SEL == 0) ? g_Winhi  : (SEL == 1) ? g_Wh1hi : g_Wh2hi;
    const __nv_bfloat16* Blo = (SEL == 0) ? g_Winlo  : (SEL == 1) ? g_Wh1lo : g_Wh2lo;

    constexpr int ASTG = 8192;
    constexpr int BSTG = BN * 64;
    constexpr int WN   = BN / 4;
    constexpr int NFR  = WN / 16;
    constexpr int NNI  = WN / 8;

    extern __shared__ __align__(16) char dsm[];
    const uint32_t sb  = smem_u32(dsm);
    const uint32_t bAh = sb;
    const uint32_t bAl = sb + 3 * ASTG;
    const uint32_t bBh = sb + 6 * ASTG;
    const uint32_t bBl = bBh + 3 * BSTG;

    const int tid = threadIdx.x;
    const int warp = tid >> 5, lane = tid & 31;
    const int wm = warp >> 2, wn = warp & 3;
    const int m0 = blockIdx.y * 128, n0 = blockIdx.x * BN;

    float acc[4][NNI][4];
#pragma unroll
    for (int i = 0; i < 4; i++)
#pragma unroll
        for (int j = 0; j < NNI; j++)
#pragma unroll
            for (int q = 0; q < 4; q++) acc[i][j][q] = 0.f;

    const int row_off = (lane & 7) | (((lane >> 3) & 1) << 3);
    const int cc_half = lane >> 4;
    const int ldr = tid >> 2, ldc = tid & 3;
    const uint32_t oA0 = SWOFF(ldr, ldc), oA1 = SWOFF(ldr + 64, ldc);
    const int nchunk = K >> 5;

#define LOAD_STAGE(kc, bf) do {                                                 \
        int _k0 = (kc) << 5;                                                    \
        uint32_t _oa = (uint32_t)(bf) * ASTG, _ob = (uint32_t)(bf) * BSTG;      \
        size_t _g0 = (size_t)(m0 + ldr) * K + _k0 + ldc * 8;                    \
        size_t _g1 = (size_t)(m0 + ldr + 64) * K + _k0 + ldc * 8;               \
        cp16(bAh + _oa + oA0, Ahi + _g0);                                       \
        cp16(bAh + _oa + oA1, Ahi + _g1);                                       \
        cp16(bAl + _oa + oA0, Alo + _g0);                                       \
        cp16(bAl + _oa + oA1, Alo + _g1);                                       \
        size_t _gb0 = (size_t)(n0 + ldr) * K + _k0 + ldc * 8;                   \
        cp16(bBh + _ob + oA0, Bhi + _gb0);                                      \
        cp16(bBl + _ob + oA0, Blo + _gb0);                                      \
        if (BN == 128) {                                                        \
            size_t _gb1 = (size_t)(n0 + ldr + 64) * K + _k0 + ldc * 8;          \
            cp16(bBh + _ob + oA1, Bhi + _gb1);                                  \
            cp16(bBl + _ob + oA1, Blo + _gb1);                                  \
        }                                                                       \
    } while (0)

    LOAD_STAGE(0, 0); CP_COMMIT();
    LOAD_STAGE(1, 1); CP_COMMIT();

    for (int kc = 0; kc < nchunk; kc++) {
        if (kc + 1 < nchunk) { CP_WAIT(1); } else { CP_WAIT(0); }
        __syncthreads();
        if (kc + 2 < nchunk) {
            LOAD_STAGE(kc + 2, (kc + 2) % 3);
            CP_COMMIT();
        }
        const int bf = kc % 3;
        const uint32_t oa = (uint32_t)bf * ASTG, ob = (uint32_t)bf * BSTG;
#pragma unroll
        for (int s = 0; s < 2; s++) {
            const int cc = 2 * s + cc_half;
            uint32_t Afh[4][4], Afl[4][4], Bfh[4 * NFR], Bfl[4 * NFR];
#pragma unroll
            for (int mi = 0; mi < 4; mi++) {
                int r = wm * 64 + mi * 16 + row_off;
                ldsm_x4(Afh[mi], bAh + oa + SWOFF(r, cc));
                ldsm_x4(Afl[mi], bAl + oa + SWOFF(r, cc));
            }
#pragma unroll
            for (int f = 0; f < NFR; f++) {
                int r = wn * WN + f * 16 + row_off;
                ldsm_x4(Bfh + 4 * f, bBh + ob + SWOFF(r, cc));
                ldsm_x4(Bfl + 4 * f, bBl + ob + SWOFF(r, cc));
            }
#pragma unroll
            for (int mi = 0; mi < 4; mi++) {
#pragma unroll
                for (int ni = 0; ni < NNI; ni++) {
                    const int q = (ni >> 1) * 4 + (ni & 1);
                    mma16816(acc[mi][ni], Afh[mi], Bfh[q], Bfh[q + 2]);
                    mma16816(acc[mi][ni], Afh[mi], Bfl[q], Bfl[q + 2]);
                    mma16816(acc[mi][ni], Afl[mi], Bfh[q], Bfh[q + 2]);
                }
            }
        }
    }
#undef LOAD_STAGE

    const int g = lane >> 2, tg = lane & 3;
#pragma unroll
    for (int mi = 0; mi < 4; mi++) {
#pragma unroll
        for (int ni = 0; ni < NNI; ni++) {
            int col = n0 + wn * WN + ni * 8 + 2 * tg;
            float b0 = bias[col], b1 = bias[col + 1];
#pragma unroll
            for (int h = 0; h < 2; h++) {
                int row = m0 + wm * 64 + mi * 16 + g + h * 8;
                float v0 = acc[mi][ni][2 * h + 0] + b0;
                float v1 = acc[mi][ni][2 * h + 1] + b1;
                v0 = v0 > 0.f ? v0 : 0.f;
                v1 = v1 > 0.f ? v1 : 0.f;
                size_t idx = (size_t)row * N + col;
                if (SEL == 2) {
                    *reinterpret_cast<float2*>(g_xr + idx) = make_float2(v0, v1);
                } else {
                    __nv_bfloat16* Chi = (SEL == 0) ? g_h0hi : g_h1hi;
                    __nv_bfloat16* Clo = (SEL == 0) ? g_h0lo : g_h1lo;
                    __nv_bfloat162 hh, ll;
                    hh.x = __float2bfloat16(v0);
                    hh.y = __float2bfloat16(v1);
                    ll.x = __float2bfloat16(v0 - __bfloat162float(hh.x));
                    ll.y = __float2bfloat16(v1 - __bfloat162float(hh.y));
                    *reinterpret_cast<__nv_bfloat162*>(Chi + idx) = hh;
                    *reinterpret_cast<__nv_bfloat162*>(Clo + idx) = ll;
                }
            }
        }
    }
}

// -------------------- table init (grid-stride, double precision) ------------
__global__ void init_tables(const float* __restrict__ w0,
                            const float* __restrict__ w1)
{
    const double TWO_PI = 6.283185307179586476925286766559;
    int gtid = blockIdx.x * blockDim.x + threadIdx.x;
    int nthr = gridDim.x * blockDim.x;
    for (int i = gtid; i < 32768; i += nthr) {
        double s, c;
        sincos(-TWO_PI * (double)i / 32768.0, &s, &c);
        g_btw[i] = make_float2((float)c, (float)s);
    }
    for (int i = gtid; i < 85; i += nthr) {
        int Ns, off;
        if (i < 1)       { Ns = 1;  off = 0; }
        else if (i < 5)  { Ns = 4;  off = 1; }
        else if (i < 21) { Ns = 16; off = 5; }
        else             { Ns = 64; off = 21; }
        int jm = i - off;
        for (int m = 1; m <= 3; m++) {
            double s, c;
            sincos(-TWO_PI * (double)(m * jm) / (double)(4 * Ns), &s, &c);
            g_r4a[i * 3 + m - 1] = make_float2((float)c, (float)s);
        }
    }
    for (int i = gtid; i < 42; i += nthr) {
        int Ns, off;
        if (i < 2)       { Ns = 2;  off = 0; }
        else if (i < 10) { Ns = 8;  off = 2; }
        else             { Ns = 32; off = 10; }
        int jm = i - off;
        for (int m = 1; m <= 3; m++) {
            double s, c;
            sincos(-TWO_PI * (double)(m * jm) / (double)(4 * Ns), &s, &c);
            g_r4b[i * 3 + m - 1] = make_float2((float)c, (float)s);
        }
    }
    for (int i = gtid; i < 4096; i += nthr) {
        int a = i >> 6, b = i & 63;
        int t = (a * b) & 63;
        double s, c;
        sincos(-TWO_PI * (double)t / 64.0, &s, &c);
        g_dftF[i] = make_float2((float)c, (float)s);
        g_dftI[i] = make_float2((float)(c / 64.0), (float)(-s / 64.0));
    }
    for (int w = gtid; w < 64; w += nthr) {
        double pr = 0, pi = 0, mr = 0, mi = 0;
        for (int m = 0; m < 32; m++) {
            float a = w0[m * 64 + w];
            float b = w1[m * 64 + w];
            double s, c;
            sincos(TWO_PI * (double)m / 32.0, &s, &c);
            double coef = (double)b * fabs((double)a);
            if (a >= 0.0f) { pr += coef * c; pi += coef * s; }
            else           { mr += coef * c; mi += coef * s; }
        }
        g_P[w] = make_float2((float)pr, (float)pi);
        g_M[w] = make_float2((float)mr, (float)mi);
    }
}

// -------------------- batch-axis FFT, step 1: 256-pt radix-4 ----------------
// REAL=1: forward pass reads real g_xr.  REAL=0: inverse pass reads g_bufA.
template <int REAL>
__global__ __launch_bounds__(256)
void fft_b_step1(float fs)
{
    __shared__ float2 s0[8][256];
    __shared__ float2 s1[8][256];
    __shared__ float2 stw[255];
    int tid = threadIdx.x;
    int n1 = blockIdx.x;
    int c0 = blockIdx.y << 3;
    for (int i = tid; i < 255; i += 256) stw[i] = g_r4a[i];
    for (int i = tid; i < 2048; i += 256) {
        int n2 = i >> 3, ch = i & 7;
        size_t gi = (size_t)(n1 + (n2 << 7)) * 64 + c0 + ch;
        if (REAL) s0[ch][n2] = make_float2(g_xr[gi], 0.f);
        else      s0[ch][n2] = g_bufA[gi];
    }
    __syncthreads();
    float2 (*src)[256] = s0;
    float2 (*dst)[256] = s1;
#pragma unroll
    for (int st = 0; st < 4; st++) {
        const int Ns = 1 << (2 * st);
        const int off = (Ns - 1) / 3;
        for (int u = tid; u < 512; u += 256) {
            int ch = u >> 6, j = u & 63;
            int jm = j & (Ns - 1);
            int tb = (off + jm) * 3;
            float2 w1 = stw[tb], w2 = stw[tb + 1], w3 = stw[tb + 2];
            float w1y = fs * w1.y, w2y = fs * w2.y, w3y = fs * w3.y;
            float2 a = src[ch][j];
            float2 b = src[ch][j + 64];
            float2 c = src[ch][j + 128];
            float2 d = src[ch][j + 192];
            float2 bw = make_float2(b.x * w1.x - b.y * w1y, b.x * w1y + b.y * w1.x);
            float2 cw = make_float2(c.x * w2.x - c.y * w2y, c.x * w2y + c.y * w2.x);
            float2 dw = make_float2(d.x * w3.x - d.y * w3y, d.x * w3y + d.y * w3.x);
            float2 t0 = make_float2(a.x + cw.x, a.y + cw.y);
            float2 t1 = make_float2(a.x - cw.x, a.y - cw.y);
            float2 t2 = make_float2(bw.x + dw.x, bw.y + dw.y);
            float2 u3 = make_float2(bw.x - dw.x, bw.y - dw.y);
            float2 t3 = make_float2(fs * u3.y, -fs * u3.x);
            int idxD = ((j - jm) << 2) + jm;
            dst[ch][idxD]          = make_float2(t0.x + t2.x, t0.y + t2.y);
            dst[ch][idxD + Ns]     = make_float2(t1.x + t3.x, t1.y + t3.y);
            dst[ch][idxD + 2 * Ns] = make_float2(t0.x - t2.x, t0.y - t2.y);
            dst[ch][idxD + 3 * Ns] = make_float2(t1.x - t3.x, t1.y - t3.y);
        }
        __syncthreads();
        float2 (*tmp)[256] = src; src = dst; dst = tmp;
    }
    for (int i = tid; i < 2048; i += 256) {
        int k2 = i >> 3, ch = i & 7;
        float2 w = g_btw[(n1 * k2) & 32767];
        float c = w.x, s = fs * w.y;
        float2 v = src[ch][k2];
        g_Z[((size_t)k2 * 128 + n1) * 64 + c0 + ch] =
            make_float2(v.x * c - v.y * s, v.x * s + v.y * c);
    }
}

// -------------------- batch-axis FFT, step 2: 128-pt (radix-2 + 3x radix-4) -
__global__ __launch_bounds__(256)
void fft_b_step2(float fs, float scale)
{
    __shared__ float2 s0[8][128];
    __shared__ float2 s1[8][128];
    __shared__ float2 stw[126];
    int tid = threadIdx.x;
    int k2 = blockIdx.x;
    int c0 = blockIdx.y << 3;
    for (int i = tid; i < 126; i += 256) stw[i] = g_r4b[i];
    for (int i = tid; i < 1024; i += 256) {
        int n1 = i >> 3, ch = i & 7;
        s0[ch][n1] = g_Z[((size_t)k2 * 128 + n1) * 64 + c0 + ch];
    }
    __syncthreads();
    // radix-2 stage, Ns=1 (twiddle = 1)
    for (int u = tid; u < 512; u += 256) {
        int ch = u >> 6, j = u & 63;
        float2 a = s0[ch][j], b = s0[ch][j + 64];
        s1[ch][2 * j]     = make_float2(a.x + b.x, a.y + b.y);
        s1[ch][2 * j + 1] = make_float2(a.x - b.x, a.y - b.y);
    }
    __syncthreads();
    float2 (*src)[128] = s1;
    float2 (*dst)[128] = s0;
#pragma unroll
    for (int st = 0; st < 3; st++) {
        const int Ns = 2 << (2 * st);
        const int off = (Ns - 2) / 3;
        {
            int ch = tid >> 5, j = tid & 31;
            int jm = j & (Ns - 1);
            int tb = (off + jm) * 3;
            float2 w1 = stw[tb], w2 = stw[tb + 1], w3 = stw[tb + 2];
            float w1y = fs * w1.y, w2y = fs * w2.y, w3y = fs * w3.y;
            float2 a = src[ch][j];
            float2 b = src[ch][j + 32];
            float2 c = src[ch][j + 64];
            float2 d = src[ch][j + 96];
            float2 bw = make_float2(b.x * w1.x - b.y * w1y, b.x * w1y + b.y * w1.x);
            float2 cw = make_float2(c.x * w2.x - c.y * w2y, c.x * w2y + c.y * w2.x);
            float2 dw = make_float2(d.x * w3.x - d.y * w3y, d.x * w3y + d.y * w3.x);
            float2 t0 = make_float2(a.x + cw.x, a.y + cw.y);
            float2 t1 = make_float2(a.x - cw.x, a.y - cw.y);
            float2 t2 = make_float2(bw.x + dw.x, bw.y + dw.y);
            float2 u3 = make_float2(bw.x - dw.x, bw.y - dw.y);
            float2 t3 = make_float2(fs * u3.y, -fs * u3.x);
            int idxD = ((j - jm) << 2) + jm;
            dst[ch][idxD]          = make_float2(t0.x + t2.x, t0.y + t2.y);
            dst[ch][idxD + Ns]     = make_float2(t1.x + t3.x, t1.y + t3.y);
            dst[ch][idxD + 2 * Ns] = make_float2(t0.x - t2.x, t0.y - t2.y);
            dst[ch][idxD + 3 * Ns] = make_float2(t1.x - t3.x, t1.y - t3.y);
        }
        __syncthreads();
        float2 (*tmp)[128] = src; src = dst; dst = tmp;
    }
    for (int i = tid; i < 1024; i += 256) {
        int k1 = i >> 3, ch = i & 7;
        float2 v = src[ch][k1];
        g_bufB[(size_t)(k2 + (k1 << 8)) * 64 + c0 + ch] =
            make_float2(v.x * scale, v.y * scale);
    }
}

// -------------------- FNO core: row DFT-64 + P/M + lin1 + lin2 --------------
__global__ __launch_bounds__(1024)
void mid_kernel(const float* __restrict__ lin1W, const float* __restrict__ lin1b,
                const float* __restrict__ lin2W, const float* __restrict__ lin2b)
{
    __shared__ float L1t[64 * 65];
    __shared__ float L2t[64 * 65];
    __shared__ float yre[16][64], yim[16][64];
    __shared__ float2 szu[16][64];
    __shared__ float2 sP[64], sM[64];
    int tid = threadIdx.x;
    int row0 = blockIdx.x << 4;
    for (int i = tid; i < 4096; i += 1024) {
        int o = i >> 6, w = i & 63;
        L1t[o * 65 + w] = lin1W[i];
        L2t[o * 65 + w] = lin2W[i];
    }
    if (tid < 64) { sP[tid] = g_P[tid]; sM[tid] = g_M[tid]; }
    int r = tid >> 6, w = tid & 63;
    szu[r][w] = g_bufB[(size_t)(row0 + r) * 64 + w];
    __syncthreads();
    float xre = 0.f, xim = 0.f;
#pragma unroll 16
    for (int ww = 0; ww < 64; ww++) {
        float2 t = g_dftF[(ww << 6) + w];
        float2 z = szu[r][ww];
        xre += z.x * t.x - z.y * t.y;
        xim += z.x * t.y + z.y * t.x;
    }
    {
        float rp = fmaxf(xre, 0.f), rn = fmaxf(-xre, 0.f);
        float ip = fmaxf(xim, 0.f), im2 = fmaxf(-xim, 0.f);
        float2 P = sP[w], Mv = sM[w];
        yre[r][w] = rp * P.x - ip * P.y + rn * Mv.x - im2 * Mv.y;
        yim[r][w] = rp * P.y + ip * P.x + rn * Mv.y + im2 * Mv.x;
    }
    __syncthreads();
    int o = w;
    float re = lin1b[o], im = 0.f;
#pragma unroll 16
    for (int ww = 0; ww < 64; ww++) {
        float lw = L1t[o * 65 + ww];
        re = fmaf(lw, yre[r][ww], re);
        im = fmaf(lw, yim[r][ww], im);
    }
    re = fmaxf(re, 0.f);
    im = fmaxf(im, 0.f);
    __syncthreads();
    yre[r][o] = re;
    yim[r][o] = im;
    __syncthreads();
    re = lin2b[o]; im = 0.f;
#pragma unroll 16
    for (int ww = 0; ww < 64; ww++) {
        float lw = L2t[o * 65 + ww];
        re = fmaf(lw, yre[r][ww], re);
        im = fmaf(lw, yim[r][ww], im);
    }
    g_bufA[(size_t)(row0 + r) * 64 + o] = make_float2(re, im);
}

// -------------------- inverse row DFT-64 + W_out (16 rows/block) ------------
__global__ __launch_bounds__(1024)
void out_kernel(const float* __restrict__ Wout, const float* __restrict__ bout,
                float* __restrict__ outp, int interleaved)
{
    __shared__ float Wt[128 * 65];
    __shared__ float2 szu[16][64];
    int tid = threadIdx.x;
    int row0 = blockIdx.x << 4;
    for (int i = tid; i < 8192; i += 1024) {
        int f = i >> 6, w = i & 63;
        Wt[f * 65 + w] = Wout[i];
    }
    {
        int r = tid >> 6, k = tid & 63;
        szu[r][k] = g_bufB[(size_t)(row0 + r) * 64 + k];
    }
    __syncthreads();
    float ure, uim;
    {
        int r = tid >> 6, w = tid & 63;
        float re = 0.f, im = 0.f;
#pragma unroll 16
        for (int k = 0; k < 64; k++) {
            float2 t = g_dftI[(k << 6) + w];
            float2 z = szu[r][k];
            re += z.x * t.x - z.y * t.y;
            im += z.x * t.y + z.y * t.x;
        }
        ure = re; uim = im;
    }
    __syncthreads();
    {
        int r = tid >> 6, w = tid & 63;
        szu[r][w] = make_float2(ure, uim);
    }
    __syncthreads();
#pragma unroll
    for (int it = 0; it < 2; it++) {
        int idx = it * 1024 + tid;
        int r = idx >> 7, f = idx & 127;
        float re = bout[f], im = 0.f;
#pragma unroll 16
        for (int w = 0; w < 64; w++) {
            float lw = Wt[f * 65 + w];
            float2 u = szu[r][w];
            re = fmaf(lw, u.x, re);
            im = fmaf(lw, u.y, im);
        }
        size_t oidx = (size_t)(row0 + r) * 128 + f;
        if (interleaved) {
            reinterpret_cast<float2*>(outp)[oidx] = make_float2(re, im);
        } else {
            outp[oidx] = re;
        }
    }
}

// ---------------------------------------------------------------------------
extern "C" void kernel_launch(void* const* d_in, const int* in_sizes, int n_in,
                              void* d_out, int out_size)
{
    (void)in_sizes; (void)n_in;
    const float* geom  = (const float*)d_in[0];
    const float* W_in  = (const float*)d_in[1];
    const float* b_in  = (const float*)d_in[2];
    const float* W_h1  = (const float*)d_in[3];
    const float* b_h1  = (const float*)d_in[4];
    const float* W_h2  = (const float*)d_in[5];
    const float* b_h2  = (const float*)d_in[6];
    const float* w0    = (const float*)d_in[7];
    const float* w1    = (const float*)d_in[8];
    const float* lin1W = (const float*)d_in[9];
    const float* lin1b = (const float*)d_in[10];
    const float* lin2W = (const float*)d_in[11];
    const float* lin2b = (const float*)d_in[12];
    const float* Wout  = (const float*)d_in[13];
    const float* bout  = (const float*)d_in[14];

    const int GSM128 = 6 * 8192 + 6 * 128 * 64;
    const int GSM64  = 6 * 8192 + 6 * 64 * 64;
    cudaFuncSetAttribute(mma_gemm<128, 0>, cudaFuncAttributeMaxDynamicSharedMemorySize, GSM128);
    cudaFuncSetAttribute(mma_gemm<128, 1>, cudaFuncAttributeMaxDynamicSharedMemorySize, GSM128);
    cudaFuncSetAttribute(mma_gemm<64, 2>,  cudaFuncAttributeMaxDynamicSharedMemorySize, GSM64);

    init_tables<<<64, 256>>>(w0, w1);

    split_kernel<0><<<(NB * 512 / 4) / 256, 256>>>(geom, NB * 512 / 4);
    split_kernel<1><<<(1024 * 512 / 4) / 256, 256>>>(W_in, 1024 * 512 / 4);
    mma_gemm<128, 0><<<dim3(1024 / 128, NB / 128), 256, GSM128>>>(b_in, NB, 1024, 512);
    split_kernel<2><<<(512 * 1024 / 4) / 256, 256>>>(W_h1, 512 * 1024 / 4);
    mma_gemm<128, 1><<<dim3(512 / 128, NB / 128), 256, GSM128>>>(b_h1, NB, 512, 1024);
    split_kernel<3><<<(64 * 512 / 4) / 256, 256>>>(W_h2, 64 * 512 / 4);
    mma_gemm<64, 2><<<dim3(1, NB / 128), 256, GSM64>>>(b_h2, NB, 64, 512);

    // forward batch FFT directly on real g_xr (row DFT folded into mid)
    fft_b_step1<1><<<dim3(128, 8), 256>>>(1.f);
    fft_b_step2<<<dim3(256, 8), 256>>>(1.f, 1.0f);

    // FNO core: row DFT + P/M + lin1 + lin2
    mid_kernel<<<NB / 16, 1024>>>(lin1W, lin1b, lin2W, lin2b);

    // inverse batch FFT (conjugated twiddles)
    fft_b_step1<0><<<dim3(128, 8), 256>>>(-1.f);
    fft_b_step2<<<dim3(256, 8), 256>>>(-1.f, 1.0f / 32768.0f);

    // inverse row DFT-64 + output projection
    int interleaved = (out_size >= 2 * NB * 128) ? 1 : 0;
    out_kernel<<<NB / 16, 1024>>>(Wout, bout, (float*)d_out, interleaved);
}

// round 14
// speedup vs baseline: 1.9921x; 1.2830x over previous
#include <cuda_runtime.h>
#include <cuda_fp16.h>
#include <math.h>
#include <cstdint>

// ---------------------------------------------------------------------------
// FieldPredictionNetwork:  B=32768, G=512, H0=1024, H1=512, W=64, MODES=32, FD=128
// MLP GEMMs: mma.sync fp16, asymmetric 2-product (A single-level, B hi+lo),
//            CTA 128x128, BK=32, 3-stage cp.async, one barrier per chunk.
// FFT: batch-axis radix-4 Stockham; row DFT-64 fused into mid/out kernels.
// ---------------------------------------------------------------------------

#define NB 32768

// -------------------- scratch (device globals) ------------------------------
__device__ __half g_geomh[NB * 512];
__device__ __half g_Winh[1024 * 512],  g_Winl[1024 * 512];
__device__ __half g_Wh1h[512 * 1024],  g_Wh1l[512 * 1024];
__device__ __half g_Wh2h[64 * 512],    g_Wh2l[64 * 512];
__device__ __half g_h0h[NB * 1024];
__device__ __half g_h1h[NB * 512];
__device__ float  g_xr[NB * 64];
__device__ float2 g_bufA[NB * 64];
__device__ float2 g_bufB[NB * 64];
__device__ float2 g_Z[NB * 64];
__device__ float2 g_dftF[64 * 64];
__device__ float2 g_dftI[64 * 64];
__device__ float2 g_P[64];
__device__ float2 g_M[64];
__device__ float2 g_r4a[85 * 3];    // radix-4 twiddles, N=256 (Ns=1,4,16,64)
__device__ float2 g_r4b[42 * 3];    // radix-4 twiddles, N=128 (Ns=2,8,32)
__device__ float2 g_btw[32768];     // e^{-2 pi i t / 32768}

// -------------------- small PTX wrappers ------------------------------------
__device__ __forceinline__ uint32_t smem_u32(const void* p) {
    uint32_t a;
    asm("{ .reg .u64 t; cvta.to.shared.u64 t, %1; cvt.u32.u64 %0, t; }" : "=r"(a) : "l"(p));
    return a;
}
__device__ __forceinline__ void ldsm_x4(uint32_t* r, uint32_t a) {
    asm volatile("ldmatrix.sync.aligned.m8n8.x4.shared.b16 {%0,%1,%2,%3}, [%4];"
                 : "=r"(r[0]), "=r"(r[1]), "=r"(r[2]), "=r"(r[3]) : "r"(a));
}
__device__ __forceinline__ void mma16816(float* c, const uint32_t* a,
                                         uint32_t b0, uint32_t b1) {
    asm volatile("mma.sync.aligned.m16n8k16.row.col.f32.f16.f16.f32 "
                 "{%0,%1,%2,%3}, {%4,%5,%6,%7}, {%8,%9}, {%0,%1,%2,%3};"
                 : "+f"(c[0]), "+f"(c[1]), "+f"(c[2]), "+f"(c[3])
                 : "r"(a[0]), "r"(a[1]), "r"(a[2]), "r"(a[3]), "r"(b0), "r"(b1));
}
__device__ __forceinline__ void cp16(uint32_t dst, const void* src) {
    asm volatile("cp.async.cg.shared.global [%0], [%1], 16;" :: "r"(dst), "l"(src));
}
#define CP_COMMIT()  asm volatile("cp.async.commit_group;" ::: "memory")
#define CP_WAIT(n)   asm volatile("cp.async.wait_group %0;" :: "n"(n) : "memory")

// 16B-chunk XOR swizzle: row r (16b row of 32 elems = 4 chunks), chunk cc.
#define SWOFF(r, cc) ((uint32_t)((r) * 64 + (((cc) ^ (((r) >> 1) & 3)) << 4)))

// -------------------- fp32 -> fp16 conversions ------------------------------
// geom: single-level fp16 (A operand of GEMM1)
__global__ void split_geom(const float* __restrict__ src, int n4)
{
    int i = blockIdx.x * blockDim.x + threadIdx.x;
    if (i >= n4) return;
    float4 v = reinterpret_cast<const float4*>(src)[i];
    __half2 a, b;
    a.x = __float2half_rn(v.x); a.y = __float2half_rn(v.y);
    b.x = __float2half_rn(v.z); b.y = __float2half_rn(v.w);
    reinterpret_cast<__half2*>(g_geomh)[2 * i]     = a;
    reinterpret_cast<__half2*>(g_geomh)[2 * i + 1] = b;
}

// weights: two-level fp16 (hi + residual lo).  SEL 0: W_in+W_h1 combined
// (blockIdx.x < half -> W_in, else W_h1); SEL 1: W_h2.
template <int SEL>
__global__ void split_w(const float* __restrict__ srcA,
                        const float* __restrict__ srcB, int n4each)
{
    int blk = blockIdx.x;
    const float* src;
    __half *hi, *lo;
    int i;
    if (SEL == 0) {
        int half1 = gridDim.x / 2;
        if (blk < half1) { src = srcA; hi = g_Winh; lo = g_Winl; i = blk * blockDim.x + threadIdx.x; }
        else { src = srcB; hi = g_Wh1h; lo = g_Wh1l; i = (blk - half1) * blockDim.x + threadIdx.x; }
    } else {
        src = srcA; hi = g_Wh2h; lo = g_Wh2l; i = blk * blockDim.x + threadIdx.x;
    }
    if (i >= n4each) return;
    float4 v = reinterpret_cast<const float4*>(src)[i];
    __half h0 = __float2half_rn(v.x), h1 = __float2half_rn(v.y);
    __half h2 = __float2half_rn(v.z), h3 = __float2half_rn(v.w);
    __half2 a, b;
    a.x = h0; a.y = h1; b.x = h2; b.y = h3;
    reinterpret_cast<__half2*>(hi)[2 * i]     = a;
    reinterpret_cast<__half2*>(hi)[2 * i + 1] = b;
    a.x = __float2half_rn(v.x - __half2float(h0));
    a.y = __float2half_rn(v.y - __half2float(h1));
    b.x = __float2half_rn(v.z - __half2float(h2));
    b.y = __float2half_rn(v.w - __half2float(h3));
    reinterpret_cast<__half2*>(lo)[2 * i]     = a;
    reinterpret_cast<__half2*>(lo)[2 * i + 1] = b;
}

// -------------------- mma.sync fp16 2-product GEMM + bias + relu ------------
// C[M,N] = relu(A[M,K] @ B[N,K]^T + bias).  A single-level fp16; B hi+lo.
template <int BN, int SEL>
__global__ void __launch_bounds__(256, 2)
mma_gemm(const float* __restrict__ bias, int M, int N, int K)
{
    const __half* Ah = (SEL == 0) ? g_geomh : (SEL == 1) ? g_h0h : g_h1h;
    const __half* Bh = (SEL == 0) ? g_Winh  : (SEL == 1) ? g_Wh1h : g_Wh2h;
    const __half* Bl = (SEL == 0) ? g_Winl  : (SEL == 1) ? g_Wh1l : g_Wh2l;

    constexpr int ASTG = 8192;          // 128 rows x 32 fp16 = 8 KB
    constexpr int BSTG = BN * 64;
    constexpr int WN   = BN / 4;
    constexpr int NFR  = WN / 16;       // 1 (BN=64) or 2 (BN=128)
    constexpr int NNI  = WN / 8;        // 2 or 4

    extern __shared__ __align__(16) char dsm[];
    const uint32_t sb  = smem_u32(dsm);
    const uint32_t bA  = sb;                    // 3 x ASTG
    const uint32_t bBh = sb + 3 * ASTG;         // 3 x BSTG
    const uint32_t bBl = bBh + 3 * BSTG;        // 3 x BSTG

    const int tid = threadIdx.x;
    const int warp = tid >> 5, lane = tid & 31;
    const int wm = warp >> 2, wn = warp & 3;
    const int m0 = blockIdx.y * 128, n0 = blockIdx.x * BN;

    float acc[4][NNI][4];
#pragma unroll
    for (int i = 0; i < 4; i++)
#pragma unroll
        for (int j = 0; j < NNI; j++)
#pragma unroll
            for (int q = 0; q < 4; q++) acc[i][j][q] = 0.f;

    const int row_off = (lane & 7) | (((lane >> 3) & 1) << 3);
    const int cc_half = lane >> 4;
    const int ldr = tid >> 2, ldc = tid & 3;
    const uint32_t oA0 = SWOFF(ldr, ldc), oA1 = SWOFF(ldr + 64, ldc);
    const int nchunk = K >> 5;

#define LOAD_STAGE(kc, bf) do {                                                 \
        int _k0 = (kc) << 5;                                                    \
        uint32_t _oa = (uint32_t)(bf) * ASTG, _ob = (uint32_t)(bf) * BSTG;      \
        size_t _g0 = (size_t)(m0 + ldr) * K + _k0 + ldc * 8;                    \
        size_t _g1 = (size_t)(m0 + ldr + 64) * K + _k0 + ldc * 8;               \
        cp16(bA + _oa + oA0, Ah + _g0);                                         \
        cp16(bA + _oa + oA1, Ah + _g1);                                         \
        size_t _gb0 = (size_t)(n0 + ldr) * K + _k0 + ldc * 8;                   \
        cp16(bBh + _ob + oA0, Bh + _gb0);                                       \
        cp16(bBl + _ob + oA0, Bl + _gb0);                                       \
        if (BN == 128) {                                                        \
            size_t _gb1 = (size_t)(n0 + ldr + 64) * K + _k0 + ldc * 8;          \
            cp16(bBh + _ob + oA1, Bh + _gb1);                                   \
            cp16(bBl + _ob + oA1, Bl + _gb1);                                   \
        }                                                                       \
    } while (0)

    LOAD_STAGE(0, 0); CP_COMMIT();
    LOAD_STAGE(1, 1); CP_COMMIT();

    for (int kc = 0; kc < nchunk; kc++) {
        if (kc + 1 < nchunk) { CP_WAIT(1); } else { CP_WAIT(0); }
        __syncthreads();   // publish stage kc; certifies compute(kc-1) done
        if (kc + 2 < nchunk) {
            LOAD_STAGE(kc + 2, (kc + 2) % 3);
            CP_COMMIT();
        }
        const int bf = kc % 3;
        const uint32_t oa = (uint32_t)bf * ASTG, ob = (uint32_t)bf * BSTG;
#pragma unroll
        for (int s = 0; s < 2; s++) {
            const int cc = 2 * s + cc_half;
            uint32_t Af[4][4], Bfh[4 * NFR], Bfl[4 * NFR];
#pragma unroll
            for (int mi = 0; mi < 4; mi++) {
                int r = wm * 64 + mi * 16 + row_off;
                ldsm_x4(Af[mi], bA + oa + SWOFF(r, cc));
            }
#pragma unroll
            for (int f = 0; f < NFR; f++) {
                int r = wn * WN + f * 16 + row_off;
                ldsm_x4(Bfh + 4 * f, bBh + ob + SWOFF(r, cc));
                ldsm_x4(Bfl + 4 * f, bBl + ob + SWOFF(r, cc));
            }
#pragma unroll
            for (int mi = 0; mi < 4; mi++) {
#pragma unroll
                for (int ni = 0; ni < NNI; ni++) {
                    const int q = (ni >> 1) * 4 + (ni & 1);
                    mma16816(acc[mi][ni], Af[mi], Bfh[q], Bfh[q + 2]);
                    mma16816(acc[mi][ni], Af[mi], Bfl[q], Bfl[q + 2]);
                }
            }
        }
    }
#undef LOAD_STAGE

    // ---- epilogue: bias + relu; SEL 0/1 store single-level fp16 ----
    const int g = lane >> 2, tg = lane & 3;
#pragma unroll
    for (int mi = 0; mi < 4; mi++) {
#pragma unroll
        for (int ni = 0; ni < NNI; ni++) {
            int col = n0 + wn * WN + ni * 8 + 2 * tg;
            float b0 = bias[col], b1 = bias[col + 1];
#pragma unroll
            for (int h = 0; h < 2; h++) {
                int row = m0 + wm * 64 + mi * 16 + g + h * 8;
                float v0 = acc[mi][ni][2 * h + 0] + b0;
                float v1 = acc[mi][ni][2 * h + 1] + b1;
                v0 = v0 > 0.f ? v0 : 0.f;
                v1 = v1 > 0.f ? v1 : 0.f;
                size_t idx = (size_t)row * N + col;
                if (SEL == 2) {
                    *reinterpret_cast<float2*>(g_xr + idx) = make_float2(v0, v1);
                } else {
                    __half* Ch = (SEL == 0) ? g_h0h : g_h1h;
                    __half2 hh;
                    hh.x = __float2half_rn(v0);
                    hh.y = __float2half_rn(v1);
                    *reinterpret_cast<__half2*>(Ch + idx) = hh;
                }
            }
        }
    }
}

// -------------------- table init (grid-stride, double precision) ------------
__global__ void init_tables(const float* __restrict__ w0,
                            const float* __restrict__ w1)
{
    const double TWO_PI = 6.283185307179586476925286766559;
    int gtid = blockIdx.x * blockDim.x + threadIdx.x;
    int nthr = gridDim.x * blockDim.x;
    for (int i = gtid; i < 32768; i += nthr) {
        double s, c;
        sincos(-TWO_PI * (double)i / 32768.0, &s, &c);
        g_btw[i] = make_float2((float)c, (float)s);
    }
    for (int i = gtid; i < 85; i += nthr) {
        int Ns, off;
        if (i < 1)       { Ns = 1;  off = 0; }
        else if (i < 5)  { Ns = 4;  off = 1; }
        else if (i < 21) { Ns = 16; off = 5; }
        else             { Ns = 64; off = 21; }
        int jm = i - off;
        for (int m = 1; m <= 3; m++) {
            double s, c;
            sincos(-TWO_PI * (double)(m * jm) / (double)(4 * Ns), &s, &c);
            g_r4a[i * 3 + m - 1] = make_float2((float)c, (float)s);
        }
    }
    for (int i = gtid; i < 42; i += nthr) {
        int Ns, off;
        if (i < 2)       { Ns = 2;  off = 0; }
        else if (i < 10) { Ns = 8;  off = 2; }
        else             { Ns = 32; off = 10; }
        int jm = i - off;
        for (int m = 1; m <= 3; m++) {
            double s, c;
            sincos(-TWO_PI * (double)(m * jm) / (double)(4 * Ns), &s, &c);
            g_r4b[i * 3 + m - 1] = make_float2((float)c, (float)s);
        }
    }
    for (int i = gtid; i < 4096; i += nthr) {
        int a = i >> 6, b = i & 63;
        int t = (a * b) & 63;
        double s, c;
        sincos(-TWO_PI * (double)t / 64.0, &s, &c);
        g_dftF[i] = make_float2((float)c, (float)s);
        g_dftI[i] = make_float2((float)(c / 64.0), (float)(-s / 64.0));
    }
    for (int w = gtid; w < 64; w += nthr) {
        double pr = 0, pi = 0, mr = 0, mi = 0;
        for (int m = 0; m < 32; m++) {
            float a = w0[m * 64 + w];
            float b = w1[m * 64 + w];
            double s, c;
            sincos(TWO_PI * (double)m / 32.0, &s, &c);
            double coef = (double)b * fabs((double)a);
            if (a >= 0.0f) { pr += coef * c; pi += coef * s; }
            else           { mr += coef * c; mi += coef * s; }
        }
        g_P[w] = make_float2((float)pr, (float)pi);
        g_M[w] = make_float2((float)mr, (float)mi);
    }
}

// -------------------- batch-axis FFT, step 1: 256-pt radix-4 ----------------
template <int REAL>
__global__ __launch_bounds__(256)
void fft_b_step1(float fs)
{
    __shared__ float2 s0[8][256];
    __shared__ float2 s1[8][256];
    __shared__ float2 stw[255];
    int tid = threadIdx.x;
    int n1 = blockIdx.x;
    int c0 = blockIdx.y << 3;
    for (int i = tid; i < 255; i += 256) stw[i] = g_r4a[i];
    for (int i = tid; i < 2048; i += 256) {
        int n2 = i >> 3, ch = i & 7;
        size_t gi = (size_t)(n1 + (n2 << 7)) * 64 + c0 + ch;
        if (REAL) s0[ch][n2] = make_float2(g_xr[gi], 0.f);
        else      s0[ch][n2] = g_bufA[gi];
    }
    __syncthreads();
    float2 (*src)[256] = s0;
    float2 (*dst)[256] = s1;
#pragma unroll
    for (int st = 0; st < 4; st++) {
        const int Ns = 1 << (2 * st);
        const int off = (Ns - 1) / 3;
        for (int u = tid; u < 512; u += 256) {
            int ch = u >> 6, j = u & 63;
            int jm = j & (Ns - 1);
            int tb = (off + jm) * 3;
            float2 w1 = stw[tb], w2 = stw[tb + 1], w3 = stw[tb + 2];
            float w1y = fs * w1.y, w2y = fs * w2.y, w3y = fs * w3.y;
            float2 a = src[ch][j];
            float2 b = src[ch][j + 64];
            float2 c = src[ch][j + 128];
            float2 d = src[ch][j + 192];
            float2 bw = make_float2(b.x * w1.x - b.y * w1y, b.x * w1y + b.y * w1.x);
            float2 cw = make_float2(c.x * w2.x - c.y * w2y, c.x * w2y + c.y * w2.x);
            float2 dw = make_float2(d.x * w3.x - d.y * w3y, d.x * w3y + d.y * w3.x);
            float2 t0 = make_float2(a.x + cw.x, a.y + cw.y);
            float2 t1 = make_float2(a.x - cw.x, a.y - cw.y);
            float2 t2 = make_float2(bw.x + dw.x, bw.y + dw.y);
            float2 u3 = make_float2(bw.x - dw.x, bw.y - dw.y);
            float2 t3 = make_float2(fs * u3.y, -fs * u3.x);
            int idxD = ((j - jm) << 2) + jm;
            dst[ch][idxD]          = make_float2(t0.x + t2.x, t0.y + t2.y);
            dst[ch][idxD + Ns]     = make_float2(t1.x + t3.x, t1.y + t3.y);
            dst[ch][idxD + 2 * Ns] = make_float2(t0.x - t2.x, t0.y - t2.y);
            dst[ch][idxD + 3 * Ns] = make_float2(t1.x - t3.x, t1.y - t3.y);
        }
        __syncthreads();
        float2 (*tmp)[256] = src; src = dst; dst = tmp;
    }
    for (int i = tid; i < 2048; i += 256) {
        int k2 = i >> 3, ch = i & 7;
        float2 w = g_btw[(n1 * k2) & 32767];
        float c = w.x, s = fs * w.y;
        float2 v = src[ch][k2];
        g_Z[((size_t)k2 * 128 + n1) * 64 + c0 + ch] =
            make_float2(v.x * c - v.y * s, v.x * s + v.y * c);
    }
}

// -------------------- batch-axis FFT, step 2: 128-pt (radix-2 + 3x radix-4) -
__global__ __launch_bounds__(256)
void fft_b_step2(float fs, float scale)
{
    __shared__ float2 s0[8][128];
    __shared__ float2 s1[8][128];
    __shared__ float2 stw[126];
    int tid = threadIdx.x;
    int k2 = blockIdx.x;
    int c0 = blockIdx.y << 3;
    for (int i = tid; i < 126; i += 256) stw[i] = g_r4b[i];
    for (int i = tid; i < 1024; i += 256) {
        int n1 = i >> 3, ch = i & 7;
        s0[ch][n1] = g_Z[((size_t)k2 * 128 + n1) * 64 + c0 + ch];
    }
    __syncthreads();
    for (int u = tid; u < 512; u += 256) {
        int ch = u >> 6, j = u & 63;
        float2 a = s0[ch][j], b = s0[ch][j + 64];
        s1[ch][2 * j]     = make_float2(a.x + b.x, a.y + b.y);
        s1[ch][2 * j + 1] = make_float2(a.x - b.x, a.y - b.y);
    }
    __syncthreads();
    float2 (*src)[128] = s1;
    float2 (*dst)[128] = s0;
#pragma unroll
    for (int st = 0; st < 3; st++) {
        const int Ns = 2 << (2 * st);
        const int off = (Ns - 2) / 3;
        {
            int ch = tid >> 5, j = tid & 31;
            int jm = j & (Ns - 1);
            int tb = (off + jm) * 3;
            float2 w1 = stw[tb], w2 = stw[tb + 1], w3 = stw[tb + 2];
            float w1y = fs * w1.y, w2y = fs * w2.y, w3y = fs * w3.y;
            float2 a = src[ch][j];
            float2 b = src[ch][j + 32];
            float2 c = src[ch][j + 64];
            float2 d = src[ch][j + 96];
            float2 bw = make_float2(b.x * w1.x - b.y * w1y, b.x * w1y + b.y * w1.x);
            float2 cw = make_float2(c.x * w2.x - c.y * w2y, c.x * w2y + c.y * w2.x);
            float2 dw = make_float2(d.x * w3.x - d.y * w3y, d.x * w3y + d.y * w3.x);
            float2 t0 = make_float2(a.x + cw.x, a.y + cw.y);
            float2 t1 = make_float2(a.x - cw.x, a.y - cw.y);
            float2 t2 = make_float2(bw.x + dw.x, bw.y + dw.y);
            float2 u3 = make_float2(bw.x - dw.x, bw.y - dw.y);
            float2 t3 = make_float2(fs * u3.y, -fs * u3.x);
            int idxD = ((j - jm) << 2) + jm;
            dst[ch][idxD]          = make_float2(t0.x + t2.x, t0.y + t2.y);
            dst[ch][idxD + Ns]     = make_float2(t1.x + t3.x, t1.y + t3.y);
            dst[ch][idxD + 2 * Ns] = make_float2(t0.x - t2.x, t0.y - t2.y);
            dst[ch][idxD + 3 * Ns] = make_float2(t1.x - t3.x, t1.y - t3.y);
        }
        __syncthreads();
        float2 (*tmp)[128] = src; src = dst; dst = tmp;
    }
    for (int i = tid; i < 1024; i += 256) {
        int k1 = i >> 3, ch = i & 7;
        float2 v = src[ch][k1];
        g_bufB[(size_t)(k2 + (k1 << 8)) * 64 + c0 + ch] =
            make_float2(v.x * scale, v.y * scale);
    }
}

// -------------------- FNO core: row DFT-64 + P/M + lin1 + lin2 --------------
__global__ __launch_bounds__(1024)
void mid_kernel(const float* __restrict__ lin1W, const float* __restrict__ lin1b,
                const float* __restrict__ lin2W, const float* __restrict__ lin2b)
{
    __shared__ float L1t[64 * 65];
    __shared__ float L2t[64 * 65];
    __shared__ float yre[16][64], yim[16][64];
    __shared__ float2 szu[16][64];
    __shared__ float2 sP[64], sM[64];
    int tid = threadIdx.x;
    int row0 = blockIdx.x << 4;
    for (int i = tid; i < 4096; i += 1024) {
        int o = i >> 6, w = i & 63;
        L1t[o * 65 + w] = lin1W[i];
        L2t[o * 65 + w] = lin2W[i];
    }
    if (tid < 64) { sP[tid] = g_P[tid]; sM[tid] = g_M[tid]; }
    int r = tid >> 6, w = tid & 63;
    szu[r][w] = g_bufB[(size_t)(row0 + r) * 64 + w];
    __syncthreads();
    float xre = 0.f, xim = 0.f;
#pragma unroll 16
    for (int ww = 0; ww < 64; ww++) {
        float2 t = g_dftF[(ww << 6) + w];
        float2 z = szu[r][ww];
        xre += z.x * t.x - z.y * t.y;
        xim += z.x * t.y + z.y * t.x;
    }
    {
        float rp = fmaxf(xre, 0.f), rn = fmaxf(-xre, 0.f);
        float ip = fmaxf(xim, 0.f), im2 = fmaxf(-xim, 0.f);
        float2 P = sP[w], Mv = sM[w];
        yre[r][w] = rp * P.x - ip * P.y + rn * Mv.x - im2 * Mv.y;
        yim[r][w] = rp * P.y + ip * P.x + rn * Mv.y + im2 * Mv.x;
    }
    __syncthreads();
    int o = w;
    float re = lin1b[o], im = 0.f;
#pragma unroll 16
    for (int ww = 0; ww < 64; ww++) {
        float lw = L1t[o * 65 + ww];
        re = fmaf(lw, yre[r][ww], re);
        im = fmaf(lw, yim[r][ww], im);
    }
    re = fmaxf(re, 0.f);
    im = fmaxf(im, 0.f);
    __syncthreads();
    yre[r][o] = re;
    yim[r][o] = im;
    __syncthreads();
    re = lin2b[o]; im = 0.f;
#pragma unroll 16
    for (int ww = 0; ww < 64; ww++) {
        float lw = L2t[o * 65 + ww];
        re = fmaf(lw, yre[r][ww], re);
        im = fmaf(lw, yim[r][ww], im);
    }
    g_bufA[(size_t)(row0 + r) * 64 + o] = make_float2(re, im);
}

// -------------------- inverse row DFT-64 + W_out (16 rows/block) ------------
__global__ __launch_bounds__(1024)
void out_kernel(const float* __restrict__ Wout, const float* __restrict__ bout,
                float* __restrict__ outp, int interleaved)
{
    __shared__ float Wt[128 * 65];
    __shared__ float2 szu[16][64];
    int tid = threadIdx.x;
    int row0 = blockIdx.x << 4;
    for (int i = tid; i < 8192; i += 1024) {
        int f = i >> 6, w = i & 63;
        Wt[f * 65 + w] = Wout[i];
    }
    {
        int r = tid >> 6, k = tid & 63;
        szu[r][k] = g_bufB[(size_t)(row0 + r) * 64 + k];
    }
    __syncthreads();
    float ure, uim;
    {
        int r = tid >> 6, w = tid & 63;
        float re = 0.f, im = 0.f;
#pragma unroll 16
        for (int k = 0; k < 64; k++) {
            float2 t = g_dftI[(k << 6) + w];
            float2 z = szu[r][k];
            re += z.x * t.x - z.y * t.y;
            im += z.x * t.y + z.y * t.x;
        }
        ure = re; uim = im;
    }
    __syncthreads();
    {
        int r = tid >> 6, w = tid & 63;
        szu[r][w] = make_float2(ure, uim);
    }
    __syncthreads();
#pragma unroll
    for (int it = 0; it < 2; it++) {
        int idx = it * 1024 + tid;
        int r = idx >> 7, f = idx & 127;
        float re = bout[f], im = 0.f;
#pragma unroll 16
        for (int w = 0; w < 64; w++) {
            float lw = Wt[f * 65 + w];
            float2 u = szu[r][w];
            re = fmaf(lw, u.x, re);
            im = fmaf(lw, u.y, im);
        }
        size_t oidx = (size_t)(row0 + r) * 128 + f;
        if (interleaved) {
            reinterpret_cast<float2*>(outp)[oidx] = make_float2(re, im);
        } else {
            outp[oidx] = re;
        }
    }
}

// ---------------------------------------------------------------------------
extern "C" void kernel_launch(void* const* d_in, const int* in_sizes, int n_in,
                              void* d_out, int out_size)
{
    (void)in_sizes; (void)n_in;
    const float* geom  = (const float*)d_in[0];
    const float* W_in  = (const float*)d_in[1];
    const float* b_in  = (const float*)d_in[2];
    const float* W_h1  = (const float*)d_in[3];
    const float* b_h1  = (const float*)d_in[4];
    const float* W_h2  = (const float*)d_in[5];
    const float* b_h2  = (const float*)d_in[6];
    const float* w0    = (const float*)d_in[7];
    const float* w1    = (const float*)d_in[8];
    const float* lin1W = (const float*)d_in[9];
    const float* lin1b = (const float*)d_in[10];
    const float* lin2W = (const float*)d_in[11];
    const float* lin2b = (const float*)d_in[12];
    const float* Wout  = (const float*)d_in[13];
    const float* bout  = (const float*)d_in[14];

    const int GSM128 = 3 * 8192 + 6 * 128 * 64;   // 73728 bytes (BN=128)
    const int GSM64  = 3 * 8192 + 6 * 64 * 64;    // 49152 bytes (BN=64)
    cudaFuncSetAttribute(mma_gemm<128, 0>, cudaFuncAttributeMaxDynamicSharedMemorySize, GSM128);
    cudaFuncSetAttribute(mma_gemm<128, 1>, cudaFuncAttributeMaxDynamicSharedMemorySize, GSM128);
    cudaFuncSetAttribute(mma_gemm<64, 2>,  cudaFuncAttributeMaxDynamicSharedMemorySize, GSM64);

    // order chosen so mma_gemm<128,1> (GEMM2) is the 4th launch = ncu capture
    split_geom<<<(NB * 512 / 4) / 256, 256>>>(geom, NB * 512 / 4);
    split_w<0><<<2 * (1024 * 512 / 4) / 256, 256>>>(W_in, W_h1, 1024 * 512 / 4);
    mma_gemm<128, 0><<<dim3(1024 / 128, NB / 128), 256, GSM128>>>(b_in, NB, 1024, 512);
    mma_gemm<128, 1><<<dim3(512 / 128, NB / 128), 256, GSM128>>>(b_h1, NB, 512, 1024);
    init_tables<<<64, 256>>>(w0, w1);
    split_w<1><<<(64 * 512 / 4) / 256, 256>>>(W_h2, nullptr, 64 * 512 / 4);
    mma_gemm<64, 2><<<dim3(1, NB / 128), 256, GSM64>>>(b_h2, NB, 64, 512);

    // forward batch FFT directly on real g_xr (row DFT folded into mid)
    fft_b_step1<1><<<dim3(128, 8), 256>>>(1.f);
    fft_b_step2<<<dim3(256, 8), 256>>>(1.f, 1.0f);

    // FNO core: row DFT + P/M + lin1 + lin2
    mid_kernel<<<NB / 16, 1024>>>(lin1W, lin1b, lin2W, lin2b);

    // inverse batch FFT (conjugated twiddles)
    fft_b_step1<0><<<dim3(128, 8), 256>>>(-1.f);
    fft_b_step2<<<dim3(256, 8), 256>>>(-1.f, 1.0f / 32768.0f);

    // inverse row DFT-64 + output projection
    int interleaved = (out_size >= 2 * NB * 128) ? 1 : 0;
    out_kernel<<<NB / 16, 1024>>>(Wout, bout, (float*)d_out, interleaved);
}

// round 15
// speedup vs baseline: 2.2168x; 1.1128x over previous
#include <cuda_runtime.h>
#include <cuda_fp16.h>
#include <math.h>
#include <cstdint>

// ---------------------------------------------------------------------------
// FieldPredictionNetwork:  B=32768, G=512, H0=1024, H1=512, W=64, MODES=32, FD=128
// MLP GEMMs: mma.sync fp16, asymmetric 2-product (A single-level, B hi+lo).
// FFT: batch-axis radix-4 Stockham; row DFT-64 fused into mid/out kernels.
// mid/out register-tiled (2x2 / 2x4) to cut shared-memory bytes per FMA.
// ---------------------------------------------------------------------------

#define NB 32768

// -------------------- scratch (device globals) ------------------------------
__device__ __half g_geomh[NB * 512];
__device__ __half g_Winh[1024 * 512],  g_Winl[1024 * 512];
__device__ __half g_Wh1h[512 * 1024],  g_Wh1l[512 * 1024];
__device__ __half g_Wh2h[64 * 512],    g_Wh2l[64 * 512];
__device__ __half g_h0h[NB * 1024];
__device__ __half g_h1h[NB * 512];
__device__ float  g_xr[NB * 64];
__device__ float2 g_bufA[NB * 64];
__device__ float2 g_bufB[NB * 64];
__device__ float2 g_Z[NB * 64];
__device__ float2 g_dftF[64 * 64];
__device__ float2 g_dftI[64 * 64];
__device__ float2 g_P[64];
__device__ float2 g_M[64];
__device__ float2 g_r4a[85 * 3];
__device__ float2 g_r4b[42 * 3];
__device__ float2 g_btw[32768];

// -------------------- small PTX wrappers ------------------------------------
__device__ __forceinline__ uint32_t smem_u32(const void* p) {
    uint32_t a;
    asm("{ .reg .u64 t; cvta.to.shared.u64 t, %1; cvt.u32.u64 %0, t; }" : "=r"(a) : "l"(p));
    return a;
}
__device__ __forceinline__ void ldsm_x4(uint32_t* r, uint32_t a) {
    asm volatile("ldmatrix.sync.aligned.m8n8.x4.shared.b16 {%0,%1,%2,%3}, [%4];"
                 : "=r"(r[0]), "=r"(r[1]), "=r"(r[2]), "=r"(r[3]) : "r"(a));
}
__device__ __forceinline__ void mma16816(float* c, const uint32_t* a,
                                         uint32_t b0, uint32_t b1) {
    asm volatile("mma.sync.aligned.m16n8k16.row.col.f32.f16.f16.f32 "
                 "{%0,%1,%2,%3}, {%4,%5,%6,%7}, {%8,%9}, {%0,%1,%2,%3};"
                 : "+f"(c[0]), "+f"(c[1]), "+f"(c[2]), "+f"(c[3])
                 : "r"(a[0]), "r"(a[1]), "r"(a[2]), "r"(a[3]), "r"(b0), "r"(b1));
}
__device__ __forceinline__ void cp16(uint32_t dst, const void* src) {
    asm volatile("cp.async.cg.shared.global [%0], [%1], 16;" :: "r"(dst), "l"(src));
}
#define CP_COMMIT()  asm volatile("cp.async.commit_group;" ::: "memory")
#define CP_WAIT(n)   asm volatile("cp.async.wait_group %0;" :: "n"(n) : "memory")

#define SWOFF(r, cc) ((uint32_t)((r) * 64 + (((cc) ^ (((r) >> 1) & 3)) << 4)))

// -------------------- fp32 -> fp16 conversions ------------------------------
__global__ void split_geom(const float* __restrict__ src, int n4)
{
    int i = blockIdx.x * blockDim.x + threadIdx.x;
    if (i >= n4) return;
    float4 v = reinterpret_cast<const float4*>(src)[i];
    __half2 a, b;
    a.x = __float2half_rn(v.x); a.y = __float2half_rn(v.y);
    b.x = __float2half_rn(v.z); b.y = __float2half_rn(v.w);
    reinterpret_cast<__half2*>(g_geomh)[2 * i]     = a;
    reinterpret_cast<__half2*>(g_geomh)[2 * i + 1] = b;
}

template <int SEL>
__global__ void split_w(const float* __restrict__ srcA,
                        const float* __restrict__ srcB, int n4each)
{
    int blk = blockIdx.x;
    const float* src;
    __half *hi, *lo;
    int i;
    if (SEL == 0) {
        int half1 = gridDim.x / 2;
        if (blk < half1) { src = srcA; hi = g_Winh; lo = g_Winl; i = blk * blockDim.x + threadIdx.x; }
        else { src = srcB; hi = g_Wh1h; lo = g_Wh1l; i = (blk - half1) * blockDim.x + threadIdx.x; }
    } else {
        src = srcA; hi = g_Wh2h; lo = g_Wh2l; i = blk * blockDim.x + threadIdx.x;
    }
    if (i >= n4each) return;
    float4 v = reinterpret_cast<const float4*>(src)[i];
    __half h0 = __float2half_rn(v.x), h1 = __float2half_rn(v.y);
    __half h2 = __float2half_rn(v.z), h3 = __float2half_rn(v.w);
    __half2 a, b;
    a.x = h0; a.y = h1; b.x = h2; b.y = h3;
    reinterpret_cast<__half2*>(hi)[2 * i]     = a;
    reinterpret_cast<__half2*>(hi)[2 * i + 1] = b;
    a.x = __float2half_rn(v.x - __half2float(h0));
    a.y = __float2half_rn(v.y - __half2float(h1));
    b.x = __float2half_rn(v.z - __half2float(h2));
    b.y = __float2half_rn(v.w - __half2float(h3));
    reinterpret_cast<__half2*>(lo)[2 * i]     = a;
    reinterpret_cast<__half2*>(lo)[2 * i + 1] = b;
}

// -------------------- mma.sync fp16 2-product GEMM + bias + relu ------------
template <int BN, int SEL>
__global__ void __launch_bounds__(256, 2)
mma_gemm(const float* __restrict__ bias, int M, int N, int K)
{
    const __half* Ah = (SEL == 0) ? g_geomh : (SEL == 1) ? g_h0h : g_h1h;
    const __half* Bh = (SEL == 0) ? g_Winh  : (SEL == 1) ? g_Wh1h : g_Wh2h;
    const __half* Bl = (SEL == 0) ? g_Winl  : (SEL == 1) ? g_Wh1l : g_Wh2l;

    constexpr int ASTG = 8192;
    constexpr int BSTG = BN * 64;
    constexpr int WN   = BN / 4;
    constexpr int NFR  = WN / 16;
    constexpr int NNI  = WN / 8;

    extern __shared__ __align__(16) char dsm[];
    const uint32_t sb  = smem_u32(dsm);
    const uint32_t bA  = sb;
    const uint32_t bBh = sb + 3 * ASTG;
    const uint32_t bBl = bBh + 3 * BSTG;

    const int tid = threadIdx.x;
    const int warp = tid >> 5, lane = tid & 31;
    const int wm = warp >> 2, wn = warp & 3;
    const int m0 = blockIdx.y * 128, n0 = blockIdx.x * BN;

    float acc[4][NNI][4];
#pragma unroll
    for (int i = 0; i < 4; i++)
#pragma unroll
        for (int j = 0; j < NNI; j++)
#pragma unroll
            for (int q = 0; q < 4; q++) acc[i][j][q] = 0.f;

    const int row_off = (lane & 7) | (((lane >> 3) & 1) << 3);
    const int cc_half = lane >> 4;
    const int ldr = tid >> 2, ldc = tid & 3;
    const uint32_t oA0 = SWOFF(ldr, ldc), oA1 = SWOFF(ldr + 64, ldc);
    const int nchunk = K >> 5;

#define LOAD_STAGE(kc, bf) do {                                                 \
        int _k0 = (kc) << 5;                                                    \
        uint32_t _oa = (uint32_t)(bf) * ASTG, _ob = (uint32_t)(bf) * BSTG;      \
        size_t _g0 = (size_t)(m0 + ldr) * K + _k0 + ldc * 8;                    \
        size_t _g1 = (size_t)(m0 + ldr + 64) * K + _k0 + ldc * 8;               \
        cp16(bA + _oa + oA0, Ah + _g0);                                         \
        cp16(bA + _oa + oA1, Ah + _g1);                                         \
        size_t _gb0 = (size_t)(n0 + ldr) * K + _k0 + ldc * 8;                   \
        cp16(bBh + _ob + oA0, Bh + _gb0);                                       \
        cp16(bBl + _ob + oA0, Bl + _gb0);                                       \
        if (BN == 128) {                                                        \
            size_t _gb1 = (size_t)(n0 + ldr + 64) * K + _k0 + ldc * 8;          \
            cp16(bBh + _ob + oA1, Bh + _gb1);                                   \
            cp16(bBl + _ob + oA1, Bl + _gb1);                                   \
        }                                                                       \
    } while (0)

    LOAD_STAGE(0, 0); CP_COMMIT();
    LOAD_STAGE(1, 1); CP_COMMIT();

    for (int kc = 0; kc < nchunk; kc++) {
        if (kc + 1 < nchunk) { CP_WAIT(1); } else { CP_WAIT(0); }
        __syncthreads();
        if (kc + 2 < nchunk) {
            LOAD_STAGE(kc + 2, (kc + 2) % 3);
            CP_COMMIT();
        }
        const int bf = kc % 3;
        const uint32_t oa = (uint32_t)bf * ASTG, ob = (uint32_t)bf * BSTG;
#pragma unroll
        for (int s = 0; s < 2; s++) {
            const int cc = 2 * s + cc_half;
            uint32_t Af[4][4], Bfh[4 * NFR], Bfl[4 * NFR];
#pragma unroll
            for (int mi = 0; mi < 4; mi++) {
                int r = wm * 64 + mi * 16 + row_off;
                ldsm_x4(Af[mi], bA + oa + SWOFF(r, cc));
            }
#pragma unroll
            for (int f = 0; f < NFR; f++) {
                int r = wn * WN + f * 16 + row_off;
                ldsm_x4(Bfh + 4 * f, bBh + ob + SWOFF(r, cc));
                ldsm_x4(Bfl + 4 * f, bBl + ob + SWOFF(r, cc));
            }
#pragma unroll
            for (int mi = 0; mi < 4; mi++) {
#pragma unroll
                for (int ni = 0; ni < NNI; ni++) {
                    const int q = (ni >> 1) * 4 + (ni & 1);
                    mma16816(acc[mi][ni], Af[mi], Bfh[q], Bfh[q + 2]);
                    mma16816(acc[mi][ni], Af[mi], Bfl[q], Bfl[q + 2]);
                }
            }
        }
    }
#undef LOAD_STAGE

    const int g = lane >> 2, tg = lane & 3;
#pragma unroll
    for (int mi = 0; mi < 4; mi++) {
#pragma unroll
        for (int ni = 0; ni < NNI; ni++) {
            int col = n0 + wn * WN + ni * 8 + 2 * tg;
            float b0 = bias[col], b1 = bias[col + 1];
#pragma unroll
            for (int h = 0; h < 2; h++) {
                int row = m0 + wm * 64 + mi * 16 + g + h * 8;
                float v0 = acc[mi][ni][2 * h + 0] + b0;
                float v1 = acc[mi][ni][2 * h + 1] + b1;
                v0 = v0 > 0.f ? v0 : 0.f;
                v1 = v1 > 0.f ? v1 : 0.f;
                size_t idx = (size_t)row * N + col;
                if (SEL == 2) {
                    *reinterpret_cast<float2*>(g_xr + idx) = make_float2(v0, v1);
                } else {
                    __half* Ch = (SEL == 0) ? g_h0h : g_h1h;
                    __half2 hh;
                    hh.x = __float2half_rn(v0);
                    hh.y = __float2half_rn(v1);
                    *reinterpret_cast<__half2*>(Ch + idx) = hh;
                }
            }
        }
    }
}

// -------------------- table init (grid-stride, double precision) ------------
__global__ void init_tables(const float* __restrict__ w0,
                            const float* __restrict__ w1)
{
    const double TWO_PI = 6.283185307179586476925286766559;
    int gtid = blockIdx.x * blockDim.x + threadIdx.x;
    int nthr = gridDim.x * blockDim.x;
    for (int i = gtid; i < 32768; i += nthr) {
        double s, c;
        sincos(-TWO_PI * (double)i / 32768.0, &s, &c);
        g_btw[i] = make_float2((float)c, (float)s);
    }
    for (int i = gtid; i < 85; i += nthr) {
        int Ns, off;
        if (i < 1)       { Ns = 1;  off = 0; }
        else if (i < 5)  { Ns = 4;  off = 1; }
        else if (i < 21) { Ns = 16; off = 5; }
        else             { Ns = 64; off = 21; }
        int jm = i - off;
        for (int m = 1; m <= 3; m++) {
            double s, c;
            sincos(-TWO_PI * (double)(m * jm) / (double)(4 * Ns), &s, &c);
            g_r4a[i * 3 + m - 1] = make_float2((float)c, (float)s);
        }
    }
    for (int i = gtid; i < 42; i += nthr) {
        int Ns, off;
        if (i < 2)       { Ns = 2;  off = 0; }
        else if (i < 10) { Ns = 8;  off = 2; }
        else             { Ns = 32; off = 10; }
        int jm = i - off;
        for (int m = 1; m <= 3; m++) {
            double s, c;
            sincos(-TWO_PI * (double)(m * jm) / (double)(4 * Ns), &s, &c);
            g_r4b[i * 3 + m - 1] = make_float2((float)c, (float)s);
        }
    }
    for (int i = gtid; i < 4096; i += nthr) {
        int a = i >> 6, b = i & 63;
        int t = (a * b) & 63;
        double s, c;
        sincos(-TWO_PI * (double)t / 64.0, &s, &c);
        g_dftF[i] = make_float2((float)c, (float)s);
        g_dftI[i] = make_float2((float)(c / 64.0), (float)(-s / 64.0));
    }
    for (int w = gtid; w < 64; w += nthr) {
        double pr = 0, pi = 0, mr = 0, mi = 0;
        for (int m = 0; m < 32; m++) {
            float a = w0[m * 64 + w];
            float b = w1[m * 64 + w];
            double s, c;
            sincos(TWO_PI * (double)m / 32.0, &s, &c);
            double coef = (double)b * fabs((double)a);
            if (a >= 0.0f) { pr += coef * c; pi += coef * s; }
            else           { mr += coef * c; mi += coef * s; }
        }
        g_P[w] = make_float2((float)pr, (float)pi);
        g_M[w] = make_float2((float)mr, (float)mi);
    }
}

// -------------------- batch-axis FFT, step 1: 256-pt radix-4 ----------------
template <int REAL>
__global__ __launch_bounds__(256)
void fft_b_step1(float fs)
{
    __shared__ float2 s0[8][256];
    __shared__ float2 s1[8][256];
    __shared__ float2 stw[255];
    int tid = threadIdx.x;
    int n1 = blockIdx.x;
    int c0 = blockIdx.y << 3;
    for (int i = tid; i < 255; i += 256) stw[i] = g_r4a[i];
    for (int i = tid; i < 2048; i += 256) {
        int n2 = i >> 3, ch = i & 7;
        size_t gi = (size_t)(n1 + (n2 << 7)) * 64 + c0 + ch;
        if (REAL) s0[ch][n2] = make_float2(g_xr[gi], 0.f);
        else      s0[ch][n2] = g_bufA[gi];
    }
    __syncthreads();
    float2 (*src)[256] = s0;
    float2 (*dst)[256] = s1;
#pragma unroll
    for (int st = 0; st < 4; st++) {
        const int Ns = 1 << (2 * st);
        const int off = (Ns - 1) / 3;
        for (int u = tid; u < 512; u += 256) {
            int ch = u >> 6, j = u & 63;
            int jm = j & (Ns - 1);
            int tb = (off + jm) * 3;
            float2 w1 = stw[tb], w2 = stw[tb + 1], w3 = stw[tb + 2];
            float w1y = fs * w1.y, w2y = fs * w2.y, w3y = fs * w3.y;
            float2 a = src[ch][j];
            float2 b = src[ch][j + 64];
            float2 c = src[ch][j + 128];
            float2 d = src[ch][j + 192];
            float2 bw = make_float2(b.x * w1.x - b.y * w1y, b.x * w1y + b.y * w1.x);
            float2 cw = make_float2(c.x * w2.x - c.y * w2y, c.x * w2y + c.y * w2.x);
            float2 dw = make_float2(d.x * w3.x - d.y * w3y, d.x * w3y + d.y * w3.x);
            float2 t0 = make_float2(a.x + cw.x, a.y + cw.y);
            float2 t1 = make_float2(a.x - cw.x, a.y - cw.y);
            float2 t2 = make_float2(bw.x + dw.x, bw.y + dw.y);
            float2 u3 = make_float2(bw.x - dw.x, bw.y - dw.y);
            float2 t3 = make_float2(fs * u3.y, -fs * u3.x);
            int idxD = ((j - jm) << 2) + jm;
            dst[ch][idxD]          = make_float2(t0.x + t2.x, t0.y + t2.y);
            dst[ch][idxD + Ns]     = make_float2(t1.x + t3.x, t1.y + t3.y);
            dst[ch][idxD + 2 * Ns] = make_float2(t0.x - t2.x, t0.y - t2.y);
            dst[ch][idxD + 3 * Ns] = make_float2(t1.x - t3.x, t1.y - t3.y);
        }
        __syncthreads();
        float2 (*tmp)[256] = src; src = dst; dst = tmp;
    }
    for (int i = tid; i < 2048; i += 256) {
        int k2 = i >> 3, ch = i & 7;
        float2 w = g_btw[(n1 * k2) & 32767];
        float c = w.x, s = fs * w.y;
        float2 v = src[ch][k2];
        g_Z[((size_t)k2 * 128 + n1) * 64 + c0 + ch] =
            make_float2(v.x * c - v.y * s, v.x * s + v.y * c);
    }
}

// -------------------- batch-axis FFT, step 2: 128-pt (radix-2 + 3x radix-4) -
__global__ __launch_bounds__(256)
void fft_b_step2(float fs, float scale)
{
    __shared__ float2 s0[8][128];
    __shared__ float2 s1[8][128];
    __shared__ float2 stw[126];
    int tid = threadIdx.x;
    int k2 = blockIdx.x;
    int c0 = blockIdx.y << 3;
    for (int i = tid; i < 126; i += 256) stw[i] = g_r4b[i];
    for (int i = tid; i < 1024; i += 256) {
        int n1 = i >> 3, ch = i & 7;
        s0[ch][n1] = g_Z[((size_t)k2 * 128 + n1) * 64 + c0 + ch];
    }
    __syncthreads();
    for (int u = tid; u < 512; u += 256) {
        int ch = u >> 6, j = u & 63;
        float2 a = s0[ch][j], b = s0[ch][j + 64];
        s1[ch][2 * j]     = make_float2(a.x + b.x, a.y + b.y);
        s1[ch][2 * j + 1] = make_float2(a.x - b.x, a.y - b.y);
    }
    __syncthreads();
    float2 (*src)[128] = s1;
    float2 (*dst)[128] = s0;
#pragma unroll
    for (int st = 0; st < 3; st++) {
        const int Ns = 2 << (2 * st);
        const int off = (Ns - 2) / 3;
        {
            int ch = tid >> 5, j = tid & 31;
            int jm = j & (Ns - 1);
            int tb = (off + jm) * 3;
            float2 w1 = stw[tb], w2 = stw[tb + 1], w3 = stw[tb + 2];
            float w1y = fs * w1.y, w2y = fs * w2.y, w3y = fs * w3.y;
            float2 a = src[ch][j];
            float2 b = src[ch][j + 32];
            float2 c = src[ch][j + 64];
            float2 d = src[ch][j + 96];
            float2 bw = make_float2(b.x * w1.x - b.y * w1y, b.x * w1y + b.y * w1.x);
            float2 cw = make_float2(c.x * w2.x - c.y * w2y, c.x * w2y + c.y * w2.x);
            float2 dw = make_float2(d.x * w3.x - d.y * w3y, d.x * w3y + d.y * w3.x);
            float2 t0 = make_float2(a.x + cw.x, a.y + cw.y);
            float2 t1 = make_float2(a.x - cw.x, a.y - cw.y);
            float2 t2 = make_float2(bw.x + dw.x, bw.y + dw.y);
            float2 u3 = make_float2(bw.x - dw.x, bw.y - dw.y);
            float2 t3 = make_float2(fs * u3.y, -fs * u3.x);
            int idxD = ((j - jm) << 2) + jm;
            dst[ch][idxD]          = make_float2(t0.x + t2.x, t0.y + t2.y);
            dst[ch][idxD + Ns]     = make_float2(t1.x + t3.x, t1.y + t3.y);
            dst[ch][idxD + 2 * Ns] = make_float2(t0.x - t2.x, t0.y - t2.y);
            dst[ch][idxD + 3 * Ns] = make_float2(t1.x - t3.x, t1.y - t3.y);
        }
        __syncthreads();
        float2 (*tmp)[128] = src; src = dst; dst = tmp;
    }
    for (int i = tid; i < 1024; i += 256) {
        int k1 = i >> 3, ch = i & 7;
        float2 v = src[ch][k1];
        g_bufB[(size_t)(k2 + (k1 << 8)) * 64 + c0 + ch] =
            make_float2(v.x * scale, v.y * scale);
    }
}

// -------------------- FNO core: row DFT + P/M + lin1 + lin2 (2x2 tiled) -----
__global__ __launch_bounds__(256)
void mid_kernel(const float* __restrict__ lin1W, const float* __restrict__ lin1b,
                const float* __restrict__ lin2W, const float* __restrict__ lin2b)
{
    __shared__ float L1t[64 * 65];
    __shared__ float L2t[64 * 65];
    __shared__ float2 zc[16][64];
    __shared__ float2 yc[16][64];
    __shared__ float2 sP[64], sM[64];
    int tid = threadIdx.x;
    int row0 = blockIdx.x << 4;
    for (int i = tid; i < 4096; i += 256) {
        int o = i >> 6, w = i & 63;
        L1t[o * 65 + w] = lin1W[i];
        L2t[o * 65 + w] = lin2W[i];
    }
    if (tid < 64) { sP[tid] = g_P[tid]; sM[tid] = g_M[tid]; }
    for (int i = tid; i < 1024; i += 256) {
        int r = i >> 6, w = i & 63;
        zc[r][w] = g_bufB[(size_t)(row0 + r) * 64 + w];
    }
    __syncthreads();
    const int r0 = (tid >> 5) << 1, r1 = r0 + 1;   // rows pair
    const int w0 = tid & 31, w1 = w0 + 32;         // cols pair
    // ---- row DFT-64, 2x2 outputs ----
    float a00r = 0, a00i = 0, a01r = 0, a01i = 0;
    float a10r = 0, a10i = 0, a11r = 0, a11i = 0;
#pragma unroll 8
    for (int ww = 0; ww < 64; ww++) {
        float2 z0 = zc[r0][ww], z1 = zc[r1][ww];
        float2 t0 = g_dftF[(ww << 6) + w0], t1 = g_dftF[(ww << 6) + w1];
        a00r += z0.x * t0.x - z0.y * t0.y;  a00i += z0.x * t0.y + z0.y * t0.x;
        a01r += z0.x * t1.x - z0.y * t1.y;  a01i += z0.x * t1.y + z0.y * t1.x;
        a10r += z1.x * t0.x - z1.y * t0.y;  a10i += z1.x * t0.y + z1.y * t0.x;
        a11r += z1.x * t1.x - z1.y * t1.y;  a11i += z1.x * t1.y + z1.y * t1.x;
    }
    // ---- P/M crelu collapse ----
    {
        float2 P0 = sP[w0], M0 = sM[w0], P1 = sP[w1], M1 = sM[w1];
#define PM(xr, xi, P, Mv, out)                                              \
        {                                                                   \
            float rp = fmaxf(xr, 0.f), rn = fmaxf(-(xr), 0.f);              \
            float ip = fmaxf(xi, 0.f), iq = fmaxf(-(xi), 0.f);              \
            out = make_float2(rp * P.x - ip * P.y + rn * Mv.x - iq * Mv.y,  \
                              rp * P.y + ip * P.x + rn * Mv.y + iq * Mv.x); \
        }
        float2 y00, y01, y10, y11;
        PM(a00r, a00i, P0, M0, y00)
        PM(a01r, a01i, P1, M1, y01)
        PM(a10r, a10i, P0, M0, y10)
        PM(a11r, a11i, P1, M1, y11)
#undef PM
        yc[r0][w0] = y00; yc[r0][w1] = y01;
        yc[r1][w0] = y10; yc[r1][w1] = y11;
    }
    __syncthreads();
    // ---- lin1 (+bias, crelu), 2x2 outputs ----
    float b0 = lin1b[w0], b1 = lin1b[w1];
    float s00r = b0, s00i = 0, s01r = b1, s01i = 0;
    float s10r = b0, s10i = 0, s11r = b1, s11i = 0;
#pragma unroll 8
    for (int ww = 0; ww < 64; ww++) {
        float2 y0 = yc[r0][ww], y1 = yc[r1][ww];
        float u0 = L1t[w0 * 65 + ww], u1 = L1t[w1 * 65 + ww];
        s00r += u0 * y0.x;  s00i += u0 * y0.y;
        s01r += u1 * y0.x;  s01i += u1 * y0.y;
        s10r += u0 * y1.x;  s10i += u0 * y1.y;
        s11r += u1 * y1.x;  s11i += u1 * y1.y;
    }
    s00r = fmaxf(s00r, 0.f); s00i = fmaxf(s00i, 0.f);
    s01r = fmaxf(s01r, 0.f); s01i = fmaxf(s01i, 0.f);
    s10r = fmaxf(s10r, 0.f); s10i = fmaxf(s10i, 0.f);
    s11r = fmaxf(s11r, 0.f); s11i = fmaxf(s11i, 0.f);
    __syncthreads();     // all yc reads done
    yc[r0][w0] = make_float2(s00r, s00i);
    yc[r0][w1] = make_float2(s01r, s01i);
    yc[r1][w0] = make_float2(s10r, s10i);
    yc[r1][w1] = make_float2(s11r, s11i);
    __syncthreads();
    // ---- lin2 (+bias), 2x2 outputs -> g_bufA ----
    b0 = lin2b[w0]; b1 = lin2b[w1];
    s00r = b0; s00i = 0; s01r = b1; s01i = 0;
    s10r = b0; s10i = 0; s11r = b1; s11i = 0;
#pragma unroll 8
    for (int ww = 0; ww < 64; ww++) {
        float2 y0 = yc[r0][ww], y1 = yc[r1][ww];
        float u0 = L2t[w0 * 65 + ww], u1 = L2t[w1 * 65 + ww];
        s00r += u0 * y0.x;  s00i += u0 * y0.y;
        s01r += u1 * y0.x;  s01i += u1 * y0.y;
        s10r += u0 * y1.x;  s10i += u0 * y1.y;
        s11r += u1 * y1.x;  s11i += u1 * y1.y;
    }
    g_bufA[(size_t)(row0 + r0) * 64 + w0] = make_float2(s00r, s00i);
    g_bufA[(size_t)(row0 + r0) * 64 + w1] = make_float2(s01r, s01i);
    g_bufA[(size_t)(row0 + r1) * 64 + w0] = make_float2(s10r, s10i);
    g_bufA[(size_t)(row0 + r1) * 64 + w1] = make_float2(s11r, s11i);
}

// -------------------- inverse row DFT-64 + W_out (2x2 / 2x4 tiled) ----------
__global__ __launch_bounds__(256)
void out_kernel(const float* __restrict__ Wout, const float* __restrict__ bout,
                float* __restrict__ outp, int interleaved)
{
    __shared__ float Wt[128 * 65];
    __shared__ float2 zc[16][64];
    __shared__ float2 su[16][64];
    int tid = threadIdx.x;
    int row0 = blockIdx.x << 4;
    for (int i = tid; i < 8192; i += 256) {
        int f = i >> 6, w = i & 63;
        Wt[f * 65 + w] = Wout[i];
    }
    for (int i = tid; i < 1024; i += 256) {
        int r = i >> 6, w = i & 63;
        zc[r][w] = g_bufB[(size_t)(row0 + r) * 64 + w];
    }
    __syncthreads();
    const int r0 = (tid >> 5) << 1, r1 = r0 + 1;
    const int w0 = tid & 31, w1 = w0 + 32;
    // ---- inverse row DFT-64, 2x2 outputs ----
    float a00r = 0, a00i = 0, a01r = 0, a01i = 0;
    float a10r = 0, a10i = 0, a11r = 0, a11i = 0;
#pragma unroll 8
    for (int k = 0; k < 64; k++) {
        float2 z0 = zc[r0][k], z1 = zc[r1][k];
        float2 t0 = g_dftI[(k << 6) + w0], t1 = g_dftI[(k << 6) + w1];
        a00r += z0.x * t0.x - z0.y * t0.y;  a00i += z0.x * t0.y + z0.y * t0.x;
        a01r += z0.x * t1.x - z0.y * t1.y;  a01i += z0.x * t1.y + z0.y * t1.x;
        a10r += z1.x * t0.x - z1.y * t0.y;  a10i += z1.x * t0.y + z1.y * t0.x;
        a11r += z1.x * t1.x - z1.y * t1.y;  a11i += z1.x * t1.y + z1.y * t1.x;
    }
    su[r0][w0] = make_float2(a00r, a00i);
    su[r0][w1] = make_float2(a01r, a01i);
    su[r1][w0] = make_float2(a10r, a10i);
    su[r1][w1] = make_float2(a11r, a11i);
    __syncthreads();
    // ---- W_out projection: 2 rows x 4 f-outputs per thread ----
    const int f0 = tid & 31;   // f0, f0+32, f0+64, f0+96
    float p[2][4][2];
#pragma unroll
    for (int a = 0; a < 2; a++)
#pragma unroll
        for (int b = 0; b < 4; b++) {
            p[a][b][0] = bout[f0 + 32 * b];
            p[a][b][1] = 0.f;
        }
#pragma unroll 8
    for (int w = 0; w < 64; w++) {
        float2 u0 = su[r0][w], u1 = su[r1][w];
        float w0v = Wt[(f0)      * 65 + w];
        float w1v = Wt[(f0 + 32) * 65 + w];
        float w2v = Wt[(f0 + 64) * 65 + w];
        float w3v = Wt[(f0 + 96) * 65 + w];
        p[0][0][0] += w0v * u0.x;  p[0][0][1] += w0v * u0.y;
        p[0][1][0] += w1v * u0.x;  p[0][1][1] += w1v * u0.y;
        p[0][2][0] += w2v * u0.x;  p[0][2][1] += w2v * u0.y;
        p[0][3][0] += w3v * u0.x;  p[0][3][1] += w3v * u0.y;
        p[1][0][0] += w0v * u1.x;  p[1][0][1] += w0v * u1.y;
        p[1][1][0] += w1v * u1.x;  p[1][1][1] += w1v * u1.y;
        p[1][2][0] += w2v * u1.x;  p[1][2][1] += w2v * u1.y;
        p[1][3][0] += w3v * u1.x;  p[1][3][1] += w3v * u1.y;
    }
#pragma unroll
    for (int a = 0; a < 2; a++) {
        int row = row0 + (a == 0 ? r0 : r1);
#pragma unroll
        for (int b = 0; b < 4; b++) {
            size_t oidx = (size_t)row * 128 + f0 + 32 * b;
            if (interleaved) {
                reinterpret_cast<float2*>(outp)[oidx] = make_float2(p[a][b][0], p[a][b][1]);
            } else {
                outp[oidx] = p[a][b][0];
            }
        }
    }
}

// ---------------------------------------------------------------------------
extern "C" void kernel_launch(void* const* d_in, const int* in_sizes, int n_in,
                              void* d_out, int out_size)
{
    (void)in_sizes; (void)n_in;
    const float* geom  = (const float*)d_in[0];
    const float* W_in  = (const float*)d_in[1];
    const float* b_in  = (const float*)d_in[2];
    const float* W_h1  = (const float*)d_in[3];
    const float* b_h1  = (const float*)d_in[4];
    const float* W_h2  = (const float*)d_in[5];
    const float* b_h2  = (const float*)d_in[6];
    const float* w0    = (const float*)d_in[7];
    const float* w1    = (const float*)d_in[8];
    const float* lin1W = (const float*)d_in[9];
    const float* lin1b = (const float*)d_in[10];
    const float* lin2W = (const float*)d_in[11];
    const float* lin2b = (const float*)d_in[12];
    const float* Wout  = (const float*)d_in[13];
    const float* bout  = (const float*)d_in[14];

    const int GSM128 = 3 * 8192 + 6 * 128 * 64;   // 73728 bytes
    const int GSM64  = 3 * 8192 + 6 * 64 * 64;    // 49152 bytes
    cudaFuncSetAttribute(mma_gemm<128, 0>, cudaFuncAttributeMaxDynamicSharedMemorySize, GSM128);
    cudaFuncSetAttribute(mma_gemm<128, 1>, cudaFuncAttributeMaxDynamicSharedMemorySize, GSM128);
    cudaFuncSetAttribute(mma_gemm<64, 2>,  cudaFuncAttributeMaxDynamicSharedMemorySize, GSM64);

    // mma_gemm<128,1> (GEMM2) stays in the 4th-launch ncu capture slot
    split_geom<<<(NB * 512 / 4) / 256, 256>>>(geom, NB * 512 / 4);
    split_w<0><<<2 * (1024 * 512 / 4) / 256, 256>>>(W_in, W_h1, 1024 * 512 / 4);
    mma_gemm<128, 0><<<dim3(1024 / 128, NB / 128), 256, GSM128>>>(b_in, NB, 1024, 512);
    mma_gemm<128, 1><<<dim3(512 / 128, NB / 128), 256, GSM128>>>(b_h1, NB, 512, 1024);
    init_tables<<<64, 256>>>(w0, w1);
    split_w<1><<<(64 * 512 / 4) / 256, 256>>>(W_h2, nullptr, 64 * 512 / 4);
    mma_gemm<64, 2><<<dim3(1, NB / 128), 256, GSM64>>>(b_h2, NB, 64, 512);

    // forward batch FFT directly on real g_xr
    fft_b_step1<1><<<dim3(128, 8), 256>>>(1.f);
    fft_b_step2<<<dim3(256, 8), 256>>>(1.f, 1.0f);

    // FNO core: row DFT + P/M + lin1 + lin2
    mid_kernel<<<NB / 16, 256>>>(lin1W, lin1b, lin2W, lin2b);

    // inverse batch FFT (conjugated twiddles)
    fft_b_step1<0><<<dim3(128, 8), 256>>>(-1.f);
    fft_b_step2<<<dim3(256, 8), 256>>>(-1.f, 1.0f / 32768.0f);

    // inverse row DFT-64 + output projection
    int interleaved = (out_size >= 2 * NB * 128) ? 1 : 0;
    out_kernel<<<NB / 16, 256>>>(Wout, bout, (float*)d_out, interleaved);
}